// round 13
// baseline (speedup 1.0000x reference)
#include <cuda_runtime.h>
#include <cuda_bf16.h>
#include <cstdint>

// ---------------- device scratch (no allocations allowed) ----------------
__device__ __align__(16) float g_x1[256 * 12 * 64 * 64];          // L0 out squeezed-co fp32 [bq][48][1024][4]
__device__ __align__(16) __nv_bfloat16 g_ag1[256 * 1024 * 64];    // L0 out squeezed bf16 [b][p][ci(48,pad64)]
__device__ __align__(16) __nv_bfloat16 g_w1[9 * 64 * 64];         // L1 residual weights (K1 - I) bf16, padded
__device__ __align__(16) __nv_bfloat16 g_xg[256 * 256 * 192];     // L2 input bf16 [b][p][ci]
__device__ __align__(16) float g_xf32[256 * 192 * 256];           // L2 center add, PLANAR [b][ci][p]
__device__ __align__(16) __nv_bfloat16 g_w2[9 * 3 * 192 * 64];    // L2 residual weights (K2 - I) bf16
__device__ float g_tld[256];
__device__ float g_trT[3][9];
__device__ float g_trS[3][81];
__device__ float g_t2p[16][9];
__device__ float g_s2p[16][81];

#define X_ELEMS (256 * 192 * 16 * 16)

// ---------------- packed f32x2 helpers ----------------
__device__ __forceinline__ void ffma2(unsigned long long& d, unsigned long long a,
                                      unsigned long long b) {
    asm("fma.rn.f32x2 %0, %1, %2, %0;" : "+l"(d) : "l"(a), "l"(b));
}
__device__ __forceinline__ float2 up2(unsigned long long v) {
    float2 f;
    asm("mov.b64 {%0,%1}, %2;" : "=f"(f.x), "=f"(f.y) : "l"(v));
    return f;
}
__device__ __forceinline__ float wred(float v) {
    #pragma unroll
    for (int o = 16; o; o >>= 1) v += __shfl_xor_sync(0xffffffffu, v, o);
    return v;
}

// ---------------- PTX helpers ----------------
__device__ __forceinline__ uint32_t smem_u32(const void* p) {
    uint32_t a;
    asm("{ .reg .u64 t; cvta.to.shared.u64 t, %1; cvt.u32.u64 %0, t; }" : "=r"(a) : "l"(p));
    return a;
}
__device__ __forceinline__ void cpasync16(uint32_t dst, const void* src) {
    asm volatile("cp.async.cg.shared.global [%0], [%1], 16;" :: "r"(dst), "l"(src));
}
__device__ __forceinline__ void cpasync_commit() {
    asm volatile("cp.async.commit_group;" ::: "memory");
}
template <int N>
__device__ __forceinline__ void cpasync_wait() {
    asm volatile("cp.async.wait_group %0;" :: "n"(N) : "memory");
}
__device__ __forceinline__ void ldsm4(uint32_t* r, uint32_t addr) {
    asm volatile("ldmatrix.sync.aligned.m8n8.x4.shared.b16 {%0,%1,%2,%3}, [%4];"
                 : "=r"(r[0]), "=r"(r[1]), "=r"(r[2]), "=r"(r[3]) : "r"(addr));
}
__device__ __forceinline__ void mma16816(float* d, const uint32_t* a, const uint32_t* b) {
    asm volatile(
        "mma.sync.aligned.m16n8k16.row.col.f32.bf16.bf16.f32 "
        "{%0,%1,%2,%3}, {%4,%5,%6,%7}, {%8,%9}, {%0,%1,%2,%3};"
        : "+f"(d[0]), "+f"(d[1]), "+f"(d[2]), "+f"(d[3])
        : "r"(a[0]), "r"(a[1]), "r"(a[2]), "r"(a[3]), "r"(b[0]), "r"(b[1]));
}
__device__ __forceinline__ uint32_t swz(uint32_t off) { return off ^ ((off >> 3) & 0x70); }

// ---------------- trace accumulation (partial pair range) ----------------
__device__ void trace_accum(const float* __restrict__ K, int c, int lo, int hi,
                            float* __restrict__ gT, float* __restrict__ gS) {
    __shared__ float shS[81];
    __shared__ float shT[9];
    const int tid = threadIdx.x;
    if (tid < 81) shS[tid] = 0.f;
    if (tid < 9) shT[tid] = 0.f;
    __syncthreads();
    float a81[81], t9[9];
    #pragma unroll
    for (int k = 0; k < 81; k++) a81[k] = 0.f;
    #pragma unroll
    for (int k = 0; k < 9; k++) t9[k] = 0.f;
    for (int idx = lo + tid; idx < hi; idx += 256) {
        int i = idx / c, j = idx - i * c;
        const float* Ka = K + (size_t)(i * c + j) * 9;
        const float* Kb = K + (size_t)(j * c + i) * 9;
        float av[9], bv[9];
        #pragma unroll
        for (int a = 0; a < 9; a++) { av[a] = Ka[a]; bv[a] = Kb[a]; }
        #pragma unroll
        for (int a = 0; a < 9; a++)
            #pragma unroll
            for (int b = 0; b < 9; b++) a81[a * 9 + b] += av[a] * bv[b];
        if (i == j) {
            #pragma unroll
            for (int a = 0; a < 9; a++) t9[a] += av[a];
        }
    }
    #pragma unroll
    for (int k = 0; k < 81; k++) atomicAdd(&shS[k], a81[k]);
    #pragma unroll
    for (int k = 0; k < 9; k++) atomicAdd(&shT[k], t9[k]);
    __syncthreads();
    if (tid < 81) gS[tid] = shS[tid];
    if (tid < 9) gT[tid] = shT[tid];
}

// ---------------- fused setup ----------------
__global__ void setup_kernel(const float* __restrict__ K0, const float* __restrict__ K1,
                             const float* __restrict__ K2) {
    int bid = blockIdx.x, tid = threadIdx.x;
    if (bid == 0) {
        g_tld[tid] = 0.f;
    } else if (bid <= 1024) {
        int idx = (bid - 1) * 256 + tid;
        uint4 z = make_uint4(0, 0, 0, 0);
        *(uint4*)(g_ag1 + (size_t)idx * 64 + 48) = z;
        *(uint4*)(g_ag1 + (size_t)idx * 64 + 56) = z;
    } else if (bid <= 1168) {
        int idx = (bid - 1025) * 256 + tid;
        int cil = idx & 63;
        int r = idx >> 6;
        int co = r % 64;
        int tap = r / 64;
        float w = 0.f;
        if (co < 48 && cil < 48) {
            w = K1[((size_t)co * 48 + cil) * 9 + tap];
            if (tap == 4 && cil == co) w -= 1.0f;
        }
        g_w1[idx] = __float2bfloat16(w);
    } else if (bid <= 2464) {
        int idx = (bid - 1169) * 256 + tid;
        int cil = idx & 63;
        int r = idx >> 6;
        int co = r % 192;
        int q = r / 192;
        int cc = q % 3;
        int tap = q / 3;
        int ci = cc * 64 + cil;
        float w = K2[((size_t)co * 192 + ci) * 9 + tap];
        if (tap == 4 && ci == co) w -= 1.0f;
        g_w2[idx] = __float2bfloat16(w);
    } else if (bid == 2465) {
        trace_accum(K0, 12, 0, 144, g_trT[0], g_trS[0]);
    } else if (bid == 2466) {
        trace_accum(K1, 48, 0, 2304, g_trT[1], g_trS[1]);
    } else {
        int blk = bid - 2467;
        trace_accum(K2, 192, blk * 2304, (blk + 1) * 2304, g_t2p[blk], g_s2p[blk]);
    }
}

// ---------------- finalize ----------------
__device__ __forceinline__ float2 cmul(float2 a, float2 b) {
    return make_float2(a.x * b.x - a.y * b.y, a.x * b.y + a.y * b.x);
}

__global__ void fin_kernel(const float* __restrict__ a0, const float* __restrict__ a1,
                           const float* __restrict__ a2, float* __restrict__ out) {
    __shared__ float shT[9], shS[81], red[8];
    __shared__ float stot;
    const int tid = threadIdx.x;
    float part = 0.f;
    #pragma unroll 1
    for (int L = 0; L < 3; L++) {
        const float* als = (L == 0) ? a0 : ((L == 1) ? a1 : a2);
        const int c = (L == 0) ? 12 : ((L == 1) ? 48 : 192);
        const int n = (L == 0) ? 64 : ((L == 1) ? 32 : 16);
        __syncthreads();
        if (tid < 9) {
            float s;
            if (L < 2) s = g_trT[L][tid];
            else {
                s = 0.f;
                #pragma unroll
                for (int p = 0; p < 16; p++) s += g_t2p[p][tid];
            }
            shT[tid] = s;
        }
        if (tid < 81) {
            float s;
            if (L < 2) s = g_trS[L][tid];
            else {
                s = 0.f;
                #pragma unroll
                for (int p = 0; p < 16; p++) s += g_s2p[p][tid];
            }
            shS[tid] = s;
        }
        __syncthreads();
        for (int f = tid; f < n * n; f += 256) {
            int u = f / n, v = f - u * n;
            float su, cu, sv, cv;
            sincosf(-6.283185307179586f * (float)u / (float)n, &su, &cu);
            sincosf(-6.283185307179586f * (float)v / (float)n, &sv, &cv);
            float2 eu = make_float2(cu, su), ev = make_float2(cv, sv);
            float2 pU[3] = {make_float2(1.f, 0.f), eu, cmul(eu, eu)};
            float2 pV[3] = {make_float2(1.f, 0.f), ev, cmul(ev, ev)};
            float2 ph[9];
            #pragma unroll
            for (int dy = 0; dy < 3; dy++)
                #pragma unroll
                for (int dx = 0; dx < 3; dx++) ph[dy * 3 + dx] = cmul(pU[dy], pV[dx]);
            float2 T = make_float2(0.f, 0.f), T2 = make_float2(0.f, 0.f);
            #pragma unroll
            for (int a = 0; a < 9; a++) {
                T.x += shT[a] * ph[a].x;
                T.y += shT[a] * ph[a].y;
            }
            #pragma unroll
            for (int a = 0; a < 9; a++) {
                float2 inner = make_float2(0.f, 0.f);
                #pragma unroll
                for (int b = 0; b < 9; b++) {
                    float s = shS[a * 9 + b];
                    inner.x += s * ph[b].x;
                    inner.y += s * ph[b].y;
                }
                float2 pi = cmul(ph[a], inner);
                T2.x += pi.x;
                T2.y += pi.y;
            }
            float2 e1 = cmul(pU[1], pV[1]);
            e1.y = -e1.y;
            float2 e2 = cmul(e1, e1);
            float A = e1.x * T.x - e1.y * T.y;
            float B = e2.x * T2.x - e2.y * T2.y;
            part += 2.f * A - 1.5f * (float)c - 0.5f * B;
        }
        float as = 0.f;
        for (int k = tid; k < c; k += 256) as += als[k];
        part += (float)(n * n) * as;
    }
    float w = wred(part);
    if ((tid & 31) == 0) red[tid >> 5] = w;
    __syncthreads();
    if (tid == 0) {
        float s = 0.f;
        #pragma unroll
        for (int q = 0; q < 8; q++) s += red[q];
        stot = s;
    }
    __syncthreads();
    out[X_ELEMS + tid] = stot + g_tld[tid];
}

// ---------------- layer 0: fused FFMA conv (verified R12) ----------------
__global__ void __launch_bounds__(256, 2)
conv_layer0(const float* __restrict__ X, const float* __restrict__ Kw,
            const float* __restrict__ cb, const float* __restrict__ ab,
            const float* __restrict__ als, float* __restrict__ Y,
            __nv_bfloat16* __restrict__ YB) {
    constexpr int CPREV = 3, N = 64, CI_CHUNK = 12, OUT_BLK = 12;
    constexpr int CIN = 12, H = 128;
    constexpr int S_FLOATS = CI_CHUNK * 324 * 4;
    extern __shared__ float smem[];
    float* S = smem;
    float2* KS = (float2*)(smem + S_FLOATS);
    float* sE = (float*)(KS + CI_CHUNK * 9 * OUT_BLK);
    float* sAb = sE + OUT_BLK;

    const int tid = threadIdx.x;
    const int bq = blockIdx.x;
    const int b0 = bq * 4;
    constexpr int TILES_X = N / 16;
    const int ty = (blockIdx.y / TILES_X) * 16;
    const int tx = (blockIdx.y % TILES_X) * 16;
    const int py = tid >> 4, px = tid & 15;

    if (tid < OUT_BLK) {
        sE[tid] = expf(als[tid]);
        sAb[tid] = ab[tid];
    }

    unsigned long long accA[OUT_BLK], accB[OUT_BLK];
    #pragma unroll
    for (int o = 0; o < OUT_BLK; o++) { accA[o] = 0ull; accB[o] = 0ull; }

    {
        __syncthreads();
        for (int idx = tid; idx < CI_CHUNK * 324; idx += 256) {
            int ci = idx / 324;
            int rem = idx - ci * 324;
            int yy = rem / 18, xx = rem - yy * 18;
            int g = ci / CPREV;
            int cc = ci - g * CPREV;
            int gy = ty + yy - 1;
            if (gy < 0) gy += N;
            if (gy >= N) gy -= N;
            int gx = tx + xx - 1;
            if (gx < 0) gx += N;
            if (gx >= N) gx -= N;
            int sy = 2 * gy + (g & 1);
            int sx = 2 * gx + ((g ^ (g >> 1)) & 1);
            size_t base = ((size_t)cc * H + sy) * H + sx;
            size_t bstr = (size_t)CPREV * H * H;
            float4 val;
            val.x = X[base + (size_t)(b0 + 0) * bstr];
            val.y = X[base + (size_t)(b0 + 1) * bstr];
            val.z = X[base + (size_t)(b0 + 2) * bstr];
            val.w = X[base + (size_t)(b0 + 3) * bstr];
            *(float4*)(S + idx * 4) = val;
        }
        for (int idx = tid; idx < CI_CHUNK * 9 * OUT_BLK; idx += 256) {
            int ci = idx / (9 * OUT_BLK);
            int rem = idx - ci * 9 * OUT_BLK;
            int tap = rem / OUT_BLK;
            int o = rem - tap * OUT_BLK;
            float k = Kw[((size_t)o * CIN + ci) * 9 + tap];
            KS[idx] = make_float2(k, k);
        }
        __syncthreads();

        #pragma unroll 1
        for (int ci = 0; ci < CI_CHUNK; ci++) {
            const float* Sci = S + ci * 1296;
            const float2* Kci = KS + ci * 9 * OUT_BLK;
            #pragma unroll
            for (int tap = 0; tap < 9; tap++) {
                int dy = tap / 3, dx = tap - dy * 3;
                ulonglong2 v =
                    *(const ulonglong2*)(Sci + ((py + dy) * 18 + (px + dx)) * 4);
                #pragma unroll
                for (int o = 0; o < OUT_BLK; o += 2) {
                    ulonglong2 kk = *(const ulonglong2*)(Kci + tap * OUT_BLK + o);
                    ffma2(accA[o], kk.x, v.x);
                    ffma2(accB[o], kk.x, v.y);
                    ffma2(accA[o + 1], kk.y, v.x);
                    ffma2(accB[o + 1], kk.y, v.y);
                }
            }
        }
    }

    const int i = ty + py, j = tx + px;
    const int y = i >> 1, x = j >> 1;
    const int hs = i & 1, ws = j & 1;
    const int g = (hs == ws) ? hs : (2 + hs);
    const int p = y * 32 + x;
    float ld[4] = {0.f, 0.f, 0.f, 0.f};
    uint32_t pk[6][4];

    #pragma unroll
    for (int o = 0; o < OUT_BLK; o += 2) {
        float e0 = sE[o], a0v = sAb[o];
        float e1 = sE[o + 1], a1v = sAb[o + 1];
        float c0v = cb[((size_t)o * N + i) * N + j];
        float c1v = cb[((size_t)(o + 1) * N + i) * N + j];
        float2 pA0 = up2(accA[o]), pB0 = up2(accB[o]);
        float2 pA1 = up2(accA[o + 1]), pB1 = up2(accB[o + 1]);
        float z0[4] = {pA0.x, pA0.y, pB0.x, pB0.y};
        float z1[4] = {pA1.x, pA1.y, pB1.x, pB1.y};
        float t0[4], t1[4];
        #pragma unroll
        for (int nb = 0; nb < 4; nb++) {
            t0[nb] = tanhf((z0[nb] + c0v) * e0 + a0v);
            t1[nb] = tanhf((z1[nb] + c1v) * e1 + a1v);
            ld[nb] += log1pf(-t0[nb] * t0[nb]) + log1pf(-t1[nb] * t1[nb]);
            __nv_bfloat162 p2;
            p2.x = __float2bfloat16(t0[nb]);
            p2.y = __float2bfloat16(t1[nb]);
            pk[o >> 1][nb] = *(uint32_t*)&p2;
        }
        *(float4*)(Y + (((size_t)bq * 48 + g * 12 + o) * 1024 + p) * 4) =
            make_float4(t0[0], t0[1], t0[2], t0[3]);
        *(float4*)(Y + (((size_t)bq * 48 + g * 12 + o + 1) * 1024 + p) * 4) =
            make_float4(t1[0], t1[1], t1[2], t1[3]);
    }

    {
        #pragma unroll
        for (int nb = 0; nb < 4; nb++) {
            size_t base = ((size_t)(b0 + nb) * 1024 + p) * 64 + g * 12;
            *(uint2*)(YB + base) = make_uint2(pk[0][nb], pk[1][nb]);
            *(uint2*)(YB + base + 4) = make_uint2(pk[2][nb], pk[3][nb]);
            *(uint2*)(YB + base + 8) = make_uint2(pk[4][nb], pk[5][nb]);
        }
    }

    #pragma unroll
    for (int nb = 0; nb < 4; nb++) ld[nb] = wred(ld[nb]);
    __syncthreads();
    float* red = S;
    if ((tid & 31) == 0) {
        int w = tid >> 5;
        red[w * 4 + 0] = ld[0];
        red[w * 4 + 1] = ld[1];
        red[w * 4 + 2] = ld[2];
        red[w * 4 + 3] = ld[3];
    }
    __syncthreads();
    if (tid < 4) {
        float s = 0.f;
        #pragma unroll
        for (int w = 0; w < 8; w++) s += red[w * 4 + tid];
        atomicAdd(&g_tld[b0 + tid], s);
    }
}

// ---------------- layer 1: HMMA + smem-transposed epilogue ----------------
// mainloop smem: act halo 320x128B @0 (40KB), weights 576x128B @40960 (72KB)
// epilogue reuse: sxg bf16 [64 px][200] @0 (25.6KB), sxf fp32 [192 ci][68] @25600 (52.2KB)
#define L1_WT_BASE 40960
#define L1_SMEM 114688

__global__ void __launch_bounds__(256, 2)
l1_mma(const __nv_bfloat16* __restrict__ ag, const float* __restrict__ x1p,
       const float* __restrict__ cb, const float* __restrict__ ab,
       const float* __restrict__ als,
       __nv_bfloat16* __restrict__ xg, float* __restrict__ xf) {
    extern __shared__ char smc[];
    __shared__ float sE[48], sAb[48], red[8];
    uint32_t smem_base = smem_u32(smc);
    const int tid = threadIdx.x;
    const int lane = tid & 31, wid = tid >> 5;
    const int b = blockIdx.x;
    const int mt0 = blockIdx.y * 256;
    const int ytile0 = mt0 >> 5;
    const int m0 = (wid & 3) * 64;
    const int n0 = (wid >> 2) * 32;
    const int bq = b >> 2, nb = b & 3;
    const int pbase = mt0 >> 2;   // output pixel base (64 contiguous)

    if (tid < 48) {
        sE[tid] = expf(als[tid]);
        sAb[tid] = ab[tid];
    }

    for (int r = tid; r < 320; r += 256) {
        int yrel = r >> 5, x = r & 31;
        int yg = (ytile0 - 1 + yrel) & 31;
        const char* src = (const char*)(ag + ((size_t)b * 1024 + yg * 32 + x) * 64);
        #pragma unroll
        for (int s = 0; s < 8; s++) {
            uint32_t off = (uint32_t)r * 128 + s * 16;
            cpasync16(smem_base + swz(off), src + s * 16);
        }
    }
    for (int r = tid; r < 576; r += 256) {
        const char* src = (const char*)(g_w1 + (size_t)r * 64);
        #pragma unroll
        for (int s = 0; s < 8; s++) {
            uint32_t off = (uint32_t)r * 128 + s * 16;
            cpasync16(smem_base + L1_WT_BASE + swz(off), src + s * 16);
        }
    }
    cpasync_commit();

    float d[4][4][4];
    #pragma unroll
    for (int mt = 0; mt < 4; mt++)
        #pragma unroll
        for (int nt = 0; nt < 4; nt++)
            #pragma unroll
            for (int r = 0; r < 4; r++) d[mt][nt][r] = 0.f;

    int ply[4], plx[4];
    #pragma unroll
    for (int mt = 0; mt < 4; mt++) {
        int pl = m0 + mt * 16 + (lane & 15);
        ply[mt] = pl >> 5;
        plx[mt] = pl & 31;
    }

    cpasync_wait<0>();
    __syncthreads();

    #pragma unroll 1
    for (int c = 0; c < 9; c++) {
        int dy = c / 3 - 1, dx = c % 3 - 1;
        #pragma unroll
        for (int ks = 0; ks < 4; ks++) {
            uint32_t a[4][4];
            #pragma unroll
            for (int mt = 0; mt < 4; mt++) {
                int row = (ply[mt] + 1 + dy) * 32 + ((plx[mt] + dx) & 31);
                uint32_t off = (uint32_t)row * 128 + ks * 32 + (lane >> 4) * 16;
                ldsm4(a[mt], smem_base + swz(off));
            }
            uint32_t bf[2][4];
            #pragma unroll
            for (int nh = 0; nh < 2; nh++) {
                uint32_t row = c * 64 + n0 + nh * 16 + (lane & 7) + ((lane >> 4) << 3);
                uint32_t off = row * 128 + ks * 32 + ((lane >> 3) & 1) * 16;
                ldsm4(bf[nh], smem_base + L1_WT_BASE + swz(off));
            }
            #pragma unroll
            for (int mt = 0; mt < 4; mt++)
                #pragma unroll
                for (int nt = 0; nt < 4; nt++)
                    mma16816(d[mt][nt], a[mt], &bf[nt >> 1][(nt & 1) * 2]);
        }
    }

    __syncthreads();  // mainloop smem reads done; reuse for transpose buffers
    __nv_bfloat16* sxg = (__nv_bfloat16*)smc;   // [64][200]
    float* sxf = (float*)(smc + 25600);         // [192][68]

    float ldsum = 0.f;
    #pragma unroll
    for (int nt = 0; nt < 4; nt++) {
        int co = n0 + nt * 8 + (lane & 3) * 2;
        if (co < 48) {
            float e0 = sE[co], e1 = sE[co + 1];
            float ab0 = sAb[co], ab1 = sAb[co + 1];
            const float* xc0p = x1p + ((size_t)bq * 48 + co) * 4096 + nb;
            const float* xc1p = x1p + ((size_t)bq * 48 + co + 1) * 4096 + nb;
            #pragma unroll
            for (int mt = 0; mt < 4; mt++) {
                #pragma unroll
                for (int half = 0; half < 2; half++) {
                    int p = mt0 + m0 + mt * 16 + (lane >> 2) + half * 8;
                    float xc0 = xc0p[p * 4];
                    float xc1 = xc1p[p * 4];
                    float z0 = d[mt][nt][half * 2] + xc0 + cb[(size_t)co * 1024 + p];
                    float z1 = d[mt][nt][half * 2 + 1] + xc1 + cb[(size_t)(co + 1) * 1024 + p];
                    float t0 = tanhf(z0 * e0 + ab0);
                    float t1 = tanhf(z1 * e1 + ab1);
                    ldsum += log1pf(-t0 * t0) + log1pf(-t1 * t1);
                    int i = p >> 5, j = p & 31;
                    int y = i >> 1, x = j >> 1;
                    int hs = i & 1, ws = j & 1;
                    int g = (hs == ws) ? hs : (2 + hs);
                    int pl = (y * 16 + x) - pbase;   // 0..63
                    int ci = g * 48 + co;
                    __nv_bfloat162 pk2;
                    pk2.x = __float2bfloat16(t0);
                    pk2.y = __float2bfloat16(t1);
                    *(__nv_bfloat162*)(sxg + pl * 200 + ci) = pk2;
                    sxf[ci * 68 + pl] = t0;
                    sxf[(ci + 1) * 68 + pl] = t1;
                }
            }
        }
    }
    ldsum = wred(ldsum);
    if (lane == 0) red[wid] = ldsum;
    __syncthreads();

    // coalesced writeback: xg contiguous [64 px][192 ci]
    {
        int row = tid >> 2, qq = tid & 3;  // 96B quarters
        const uint4* src = (const uint4*)((const char*)sxg + row * 400 + qq * 96);
        uint4* dst = (uint4*)((char*)(xg + ((size_t)b * 256 + pbase + row) * 192) + qq * 96);
        #pragma unroll
        for (int k = 0; k < 6; k++) dst[k] = src[k];
    }
    // coalesced writeback: xf planar [b][192 ci][256 p], this CTA owns p [pbase, pbase+64)
    #pragma unroll
    for (int k = 0; k < 3; k++) {
        int chunk = tid + k * 256;        // < 768
        int row = chunk >> 2, part = chunk & 3;
        const float4* src = (const float4*)(sxf + row * 68 + part * 16);
        float4* dst = (float4*)(xf + ((size_t)b * 192 + row) * 256 + pbase + part * 16);
        #pragma unroll
        for (int q2 = 0; q2 < 4; q2++) dst[q2] = src[q2];
    }
    if (tid == 0) {
        float s = 0.f;
        #pragma unroll
        for (int w = 0; w < 8; w++) s += red[w];
        atomicAdd(&g_tld[b], s);
    }
}

// ---------------- layer 2: HMMA + smem-transposed epilogue ----------------
// mainloop smem: 3 act slabs 256x128B @0/32768/65536, wt dbuf @98304+buf*8192
// epilogue reuse: sbuf fp32 [64 co][260] @0 (66.6KB)
#define L2_WT_BASE 98304
#define L2_SMEM 114688

__device__ __forceinline__ void l2_stage_wt(uint32_t smem_base, int buf, int c,
                                            int co0, int tid) {
    const char* wbase = (const char*)(g_w2 + ((size_t)c * 192 + co0) * 64);
    uint32_t ra = smem_base + L2_WT_BASE + buf * 8192;
    #pragma unroll
    for (int s2 = tid; s2 < 512; s2 += 256) {
        uint32_t off = (uint32_t)s2 * 16;
        cpasync16(ra + swz(off), wbase + off);
    }
    cpasync_commit();
}

__global__ void __launch_bounds__(256, 2)
l2_mma(const __nv_bfloat16* __restrict__ xg, const float* __restrict__ xf,
       const float* __restrict__ cb, const float* __restrict__ ab,
       const float* __restrict__ als, float* __restrict__ out) {
    extern __shared__ char smc[];
    __shared__ float sE[64], sAb[64];
    uint32_t smem_base = smem_u32(smc);
    const int tid = threadIdx.x;
    const int lane = tid & 31, wid = tid >> 5;
    const int b = blockIdx.x;
    const int co0 = blockIdx.y * 64;
    const int m0 = (wid & 3) * 64;
    const int n0 = (wid >> 2) * 32;

    if (tid < 64) {
        sE[tid] = expf(als[co0 + tid]);
        sAb[tid] = ab[co0 + tid];
    }

    for (int r = tid; r < 768; r += 256) {
        int cc = r >> 8, p = r & 255;
        const char* src = (const char*)(xg + ((size_t)b * 256 + p) * 192 + cc * 64);
        uint32_t base = smem_base + cc * 32768;
        #pragma unroll
        for (int s = 0; s < 8; s++) {
            uint32_t off = (uint32_t)p * 128 + s * 16;
            cpasync16(base + swz(off), src + s * 16);
        }
    }
    l2_stage_wt(smem_base, 0, 0, co0, tid);

    float d[4][4][4];
    #pragma unroll
    for (int mt = 0; mt < 4; mt++)
        #pragma unroll
        for (int nt = 0; nt < 4; nt++)
            #pragma unroll
            for (int r = 0; r < 4; r++) d[mt][nt][r] = 0.f;

    int ply[4], plx[4];
    #pragma unroll
    for (int mt = 0; mt < 4; mt++) {
        int pl = m0 + mt * 16 + (lane & 15);
        ply[mt] = pl >> 4;
        plx[mt] = pl & 15;
    }

    #pragma unroll 1
    for (int c = 0; c < 27; c++) {
        int cur = c & 1;
        cpasync_wait<0>();
        __syncthreads();
        if (c + 1 < 27) l2_stage_wt(smem_base, 1 - cur, c + 1, co0, tid);
        int tap = c / 3, cc = c - tap * 3;
        int dy = tap / 3 - 1, dx = tap % 3 - 1;
        uint32_t actb = smem_base + cc * 32768;
        uint32_t wtb = smem_base + L2_WT_BASE + cur * 8192;
        #pragma unroll
        for (int ks = 0; ks < 4; ks++) {
            uint32_t a[4][4];
            #pragma unroll
            for (int mt = 0; mt < 4; mt++) {
                int row = ((ply[mt] + dy) & 15) * 16 + ((plx[mt] + dx) & 15);
                uint32_t off = (uint32_t)row * 128 + ks * 32 + (lane >> 4) * 16;
                ldsm4(a[mt], actb + swz(off));
            }
            uint32_t bf[2][4];
            #pragma unroll
            for (int nh = 0; nh < 2; nh++) {
                uint32_t row = n0 + nh * 16 + (lane & 7) + ((lane >> 4) << 3);
                uint32_t off = row * 128 + ks * 32 + ((lane >> 3) & 1) * 16;
                ldsm4(bf[nh], wtb + swz(off));
            }
            #pragma unroll
            for (int mt = 0; mt < 4; mt++)
                #pragma unroll
                for (int nt = 0; nt < 4; nt++)
                    mma16816(d[mt][nt], a[mt], &bf[nt >> 1][(nt & 1) * 2]);
        }
    }

    // transpose accumulators through smem, then fully-coalesced epilogue
    __syncthreads();
    float* sbuf = (float*)smc;  // [64 co][260]
    #pragma unroll
    for (int nt = 0; nt < 4; nt++) {
        int cr = n0 + nt * 8 + (lane & 3) * 2;
        #pragma unroll
        for (int mt = 0; mt < 4; mt++) {
            int p = m0 + mt * 16 + (lane >> 2);
            sbuf[cr * 260 + p] = d[mt][nt][0];
            sbuf[(cr + 1) * 260 + p] = d[mt][nt][1];
            sbuf[cr * 260 + p + 8] = d[mt][nt][2];
            sbuf[(cr + 1) * 260 + p + 8] = d[mt][nt][3];
        }
    }
    __syncthreads();
    {
        int r = tid >> 2, q = tid & 3;   // co-row 0..63, quarter 0..3 (64 p each)
        int co = co0 + r;
        float e = sE[r], abv = sAb[r];
        const float4* xfp = (const float4*)(xf + ((size_t)b * 192 + co) * 256 + q * 64);
        const float4* cbp = (const float4*)(cb + (size_t)co * 256 + q * 64);
        float4* op = (float4*)(out + ((size_t)b * 192 + co) * 256 + q * 64);
        const float* sr = sbuf + r * 260 + q * 64;
        #pragma unroll
        for (int k = 0; k < 16; k++) {
            float4 dv = *(const float4*)(sr + k * 4);
            float4 xv = xfp[k];
            float4 cv = cbp[k];
            float4 o4;
            o4.x = (dv.x + xv.x + cv.x) * e + abv;
            o4.y = (dv.y + xv.y + cv.y) * e + abv;
            o4.z = (dv.z + xv.z + cv.z) * e + abv;
            o4.w = (dv.w + xv.w + cv.w) * e + abv;
            op[k] = o4;
        }
    }
}

// ---------------- launch ----------------
extern "C" void kernel_launch(void* const* d_in, const int* in_sizes, int n_in,
                              void* d_out, int out_size) {
    const float* x = (const float*)d_in[0];
    const float* k0 = (const float*)d_in[1];
    const float* cb0 = (const float*)d_in[2];
    const float* ab0 = (const float*)d_in[3];
    const float* als0 = (const float*)d_in[4];
    const float* k1 = (const float*)d_in[5];
    const float* cb1 = (const float*)d_in[6];
    const float* ab1 = (const float*)d_in[7];
    const float* als1 = (const float*)d_in[8];
    const float* k2 = (const float*)d_in[9];
    const float* cb2 = (const float*)d_in[10];
    const float* ab2 = (const float*)d_in[11];
    const float* als2 = (const float*)d_in[12];
    float* out = (float*)d_out;

    float *x1, *xf;
    __nv_bfloat16 *ag1, *xg;
    cudaGetSymbolAddress((void**)&x1, g_x1);
    cudaGetSymbolAddress((void**)&ag1, g_ag1);
    cudaGetSymbolAddress((void**)&xg, g_xg);
    cudaGetSymbolAddress((void**)&xf, g_xf32);

    const int SM0 = 12 * 324 * 4 * 4 + 12 * 9 * 12 * 8 + 12 * 2 * 4;
    cudaFuncSetAttribute((const void*)conv_layer0,
                         cudaFuncAttributeMaxDynamicSharedMemorySize, SM0);
    cudaFuncSetAttribute((const void*)l1_mma,
                         cudaFuncAttributeMaxDynamicSharedMemorySize, L1_SMEM);
    cudaFuncSetAttribute((const void*)l2_mma,
                         cudaFuncAttributeMaxDynamicSharedMemorySize, L2_SMEM);

    setup_kernel<<<2483, 256>>>(k0, k1, k2);
    conv_layer0<<<dim3(64, 16, 1), 256, SM0>>>(x, k0, cb0, ab0, als0, x1, ag1);
    l1_mma<<<dim3(256, 4), 256, L1_SMEM>>>(ag1, x1, cb1, ab1, als1, xg, xf);
    l2_mma<<<dim3(256, 3), 256, L2_SMEM>>>(xg, xf, cb2, ab2, als2, out);
    fin_kernel<<<1, 256>>>(als0, als1, als2, out);
}

// round 14
// speedup vs baseline: 1.0436x; 1.0436x over previous
#include <cuda_runtime.h>
#include <cuda_bf16.h>
#include <cstdint>

// ---------------- device scratch (no allocations allowed) ----------------
__device__ __align__(16) float g_x1[256 * 12 * 64 * 64];          // L0 out squeezed-co fp32 [bq][48][1024][4]
__device__ __align__(16) __nv_bfloat16 g_ag1[256 * 1024 * 64];    // L0 out squeezed bf16 [b][p][ci(48,pad64)]
__device__ __align__(16) __nv_bfloat16 g_w1[9 * 64 * 64];         // L1 residual weights (K1 - I) bf16, padded
__device__ __align__(16) __nv_bfloat16 g_xg[256 * 256 * 192];     // L2 input bf16 [b][p][ci]
__device__ __align__(16) float g_xf32[256 * 256 * 192];           // same, fp32 (L2 center add) [b][p][ci]
__device__ __align__(16) __nv_bfloat16 g_w2[9 * 3 * 192 * 64];    // L2 residual weights (K2 - I) bf16
__device__ float g_tld[256];
__device__ float g_trT[3][9];
__device__ float g_trS[3][81];
__device__ float g_t2p[16][9];
__device__ float g_s2p[16][81];

#define X_ELEMS (256 * 192 * 16 * 16)

// ---------------- packed f32x2 helpers ----------------
__device__ __forceinline__ void ffma2(unsigned long long& d, unsigned long long a,
                                      unsigned long long b) {
    asm("fma.rn.f32x2 %0, %1, %2, %0;" : "+l"(d) : "l"(a), "l"(b));
}
__device__ __forceinline__ float2 up2(unsigned long long v) {
    float2 f;
    asm("mov.b64 {%0,%1}, %2;" : "=f"(f.x), "=f"(f.y) : "l"(v));
    return f;
}
__device__ __forceinline__ float wred(float v) {
    #pragma unroll
    for (int o = 16; o; o >>= 1) v += __shfl_xor_sync(0xffffffffu, v, o);
    return v;
}

// ---------------- PTX helpers ----------------
__device__ __forceinline__ uint32_t smem_u32(const void* p) {
    uint32_t a;
    asm("{ .reg .u64 t; cvta.to.shared.u64 t, %1; cvt.u32.u64 %0, t; }" : "=r"(a) : "l"(p));
    return a;
}
__device__ __forceinline__ void cpasync16(uint32_t dst, const void* src) {
    asm volatile("cp.async.cg.shared.global [%0], [%1], 16;" :: "r"(dst), "l"(src));
}
__device__ __forceinline__ void cpasync_commit() {
    asm volatile("cp.async.commit_group;" ::: "memory");
}
template <int N>
__device__ __forceinline__ void cpasync_wait() {
    asm volatile("cp.async.wait_group %0;" :: "n"(N) : "memory");
}
__device__ __forceinline__ void ldsm4(uint32_t* r, uint32_t addr) {
    asm volatile("ldmatrix.sync.aligned.m8n8.x4.shared.b16 {%0,%1,%2,%3}, [%4];"
                 : "=r"(r[0]), "=r"(r[1]), "=r"(r[2]), "=r"(r[3]) : "r"(addr));
}
__device__ __forceinline__ void mma16816(float* d, const uint32_t* a, const uint32_t* b) {
    asm volatile(
        "mma.sync.aligned.m16n8k16.row.col.f32.bf16.bf16.f32 "
        "{%0,%1,%2,%3}, {%4,%5,%6,%7}, {%8,%9}, {%0,%1,%2,%3};"
        : "+f"(d[0]), "+f"(d[1]), "+f"(d[2]), "+f"(d[3])
        : "r"(a[0]), "r"(a[1]), "r"(a[2]), "r"(a[3]), "r"(b[0]), "r"(b[1]));
}
__device__ __forceinline__ uint32_t swz(uint32_t off) { return off ^ ((off >> 3) & 0x70); }

// ---------------- trace accumulation (partial pair range) ----------------
__device__ void trace_accum(const float* __restrict__ K, int c, int lo, int hi,
                            float* __restrict__ gT, float* __restrict__ gS) {
    __shared__ float shS[81];
    __shared__ float shT[9];
    const int tid = threadIdx.x;
    if (tid < 81) shS[tid] = 0.f;
    if (tid < 9) shT[tid] = 0.f;
    __syncthreads();
    float a81[81], t9[9];
    #pragma unroll
    for (int k = 0; k < 81; k++) a81[k] = 0.f;
    #pragma unroll
    for (int k = 0; k < 9; k++) t9[k] = 0.f;
    for (int idx = lo + tid; idx < hi; idx += 256) {
        int i = idx / c, j = idx - i * c;
        const float* Ka = K + (size_t)(i * c + j) * 9;
        const float* Kb = K + (size_t)(j * c + i) * 9;
        float av[9], bv[9];
        #pragma unroll
        for (int a = 0; a < 9; a++) { av[a] = Ka[a]; bv[a] = Kb[a]; }
        #pragma unroll
        for (int a = 0; a < 9; a++)
            #pragma unroll
            for (int b = 0; b < 9; b++) a81[a * 9 + b] += av[a] * bv[b];
        if (i == j) {
            #pragma unroll
            for (int a = 0; a < 9; a++) t9[a] += av[a];
        }
    }
    #pragma unroll
    for (int k = 0; k < 81; k++) atomicAdd(&shS[k], a81[k]);
    #pragma unroll
    for (int k = 0; k < 9; k++) atomicAdd(&shT[k], t9[k]);
    __syncthreads();
    if (tid < 81) gS[tid] = shS[tid];
    if (tid < 9) gT[tid] = shT[tid];
}

// ---------------- fused setup ----------------
__global__ void setup_kernel(const float* __restrict__ K0, const float* __restrict__ K1,
                             const float* __restrict__ K2) {
    int bid = blockIdx.x, tid = threadIdx.x;
    if (bid == 0) {
        g_tld[tid] = 0.f;
    } else if (bid <= 1024) {
        int idx = (bid - 1) * 256 + tid;
        uint4 z = make_uint4(0, 0, 0, 0);
        *(uint4*)(g_ag1 + (size_t)idx * 64 + 48) = z;
        *(uint4*)(g_ag1 + (size_t)idx * 64 + 56) = z;
    } else if (bid <= 1168) {
        int idx = (bid - 1025) * 256 + tid;
        int cil = idx & 63;
        int r = idx >> 6;
        int co = r % 64;
        int tap = r / 64;
        float w = 0.f;
        if (co < 48 && cil < 48) {
            w = K1[((size_t)co * 48 + cil) * 9 + tap];
            if (tap == 4 && cil == co) w -= 1.0f;
        }
        g_w1[idx] = __float2bfloat16(w);
    } else if (bid <= 2464) {
        int idx = (bid - 1169) * 256 + tid;
        int cil = idx & 63;
        int r = idx >> 6;
        int co = r % 192;
        int q = r / 192;
        int cc = q % 3;
        int tap = q / 3;
        int ci = cc * 64 + cil;
        float w = K2[((size_t)co * 192 + ci) * 9 + tap];
        if (tap == 4 && ci == co) w -= 1.0f;
        g_w2[idx] = __float2bfloat16(w);
    } else if (bid == 2465) {
        trace_accum(K0, 12, 0, 144, g_trT[0], g_trS[0]);
    } else if (bid == 2466) {
        trace_accum(K1, 48, 0, 2304, g_trT[1], g_trS[1]);
    } else {
        int blk = bid - 2467;
        trace_accum(K2, 192, blk * 2304, (blk + 1) * 2304, g_t2p[blk], g_s2p[blk]);
    }
}

// ---------------- finalize ----------------
__device__ __forceinline__ float2 cmul(float2 a, float2 b) {
    return make_float2(a.x * b.x - a.y * b.y, a.x * b.y + a.y * b.x);
}

__global__ void fin_kernel(const float* __restrict__ a0, const float* __restrict__ a1,
                           const float* __restrict__ a2, float* __restrict__ out) {
    __shared__ float shT[9], shS[81], red[8];
    __shared__ float stot;
    const int tid = threadIdx.x;
    float part = 0.f;
    #pragma unroll 1
    for (int L = 0; L < 3; L++) {
        const float* als = (L == 0) ? a0 : ((L == 1) ? a1 : a2);
        const int c = (L == 0) ? 12 : ((L == 1) ? 48 : 192);
        const int n = (L == 0) ? 64 : ((L == 1) ? 32 : 16);
        __syncthreads();
        if (tid < 9) {
            float s;
            if (L < 2) s = g_trT[L][tid];
            else {
                s = 0.f;
                #pragma unroll
                for (int p = 0; p < 16; p++) s += g_t2p[p][tid];
            }
            shT[tid] = s;
        }
        if (tid < 81) {
            float s;
            if (L < 2) s = g_trS[L][tid];
            else {
                s = 0.f;
                #pragma unroll
                for (int p = 0; p < 16; p++) s += g_s2p[p][tid];
            }
            shS[tid] = s;
        }
        __syncthreads();
        for (int f = tid; f < n * n; f += 256) {
            int u = f / n, v = f - u * n;
            float su, cu, sv, cv;
            sincosf(-6.283185307179586f * (float)u / (float)n, &su, &cu);
            sincosf(-6.283185307179586f * (float)v / (float)n, &sv, &cv);
            float2 eu = make_float2(cu, su), ev = make_float2(cv, sv);
            float2 pU[3] = {make_float2(1.f, 0.f), eu, cmul(eu, eu)};
            float2 pV[3] = {make_float2(1.f, 0.f), ev, cmul(ev, ev)};
            float2 ph[9];
            #pragma unroll
            for (int dy = 0; dy < 3; dy++)
                #pragma unroll
                for (int dx = 0; dx < 3; dx++) ph[dy * 3 + dx] = cmul(pU[dy], pV[dx]);
            float2 T = make_float2(0.f, 0.f), T2 = make_float2(0.f, 0.f);
            #pragma unroll
            for (int a = 0; a < 9; a++) {
                T.x += shT[a] * ph[a].x;
                T.y += shT[a] * ph[a].y;
            }
            #pragma unroll
            for (int a = 0; a < 9; a++) {
                float2 inner = make_float2(0.f, 0.f);
                #pragma unroll
                for (int b = 0; b < 9; b++) {
                    float s = shS[a * 9 + b];
                    inner.x += s * ph[b].x;
                    inner.y += s * ph[b].y;
                }
                float2 pi = cmul(ph[a], inner);
                T2.x += pi.x;
                T2.y += pi.y;
            }
            float2 e1 = cmul(pU[1], pV[1]);
            e1.y = -e1.y;
            float2 e2 = cmul(e1, e1);
            float A = e1.x * T.x - e1.y * T.y;
            float B = e2.x * T2.x - e2.y * T2.y;
            part += 2.f * A - 1.5f * (float)c - 0.5f * B;
        }
        float as = 0.f;
        for (int k = tid; k < c; k += 256) as += als[k];
        part += (float)(n * n) * as;
    }
    float w = wred(part);
    if ((tid & 31) == 0) red[tid >> 5] = w;
    __syncthreads();
    if (tid == 0) {
        float s = 0.f;
        #pragma unroll
        for (int q = 0; q < 8; q++) s += red[q];
        stot = s;
    }
    __syncthreads();
    out[X_ELEMS + tid] = stot + g_tld[tid];
}

// ---------------- layer 0: fused FFMA conv (R12, now 3 CTAs/SM) ----------------
__global__ void __launch_bounds__(256, 3)
conv_layer0(const float* __restrict__ X, const float* __restrict__ Kw,
            const float* __restrict__ cb, const float* __restrict__ ab,
            const float* __restrict__ als, float* __restrict__ Y,
            __nv_bfloat16* __restrict__ YB) {
    constexpr int CPREV = 3, N = 64, CI_CHUNK = 12, OUT_BLK = 12;
    constexpr int CIN = 12, H = 128;
    constexpr int S_FLOATS = CI_CHUNK * 324 * 4;
    extern __shared__ float smem[];
    float* S = smem;
    float2* KS = (float2*)(smem + S_FLOATS);
    float* sE = (float*)(KS + CI_CHUNK * 9 * OUT_BLK);
    float* sAb = sE + OUT_BLK;

    const int tid = threadIdx.x;
    const int bq = blockIdx.x;
    const int b0 = bq * 4;
    constexpr int TILES_X = N / 16;
    const int ty = (blockIdx.y / TILES_X) * 16;
    const int tx = (blockIdx.y % TILES_X) * 16;
    const int py = tid >> 4, px = tid & 15;

    if (tid < OUT_BLK) {
        sE[tid] = expf(als[tid]);
        sAb[tid] = ab[tid];
    }

    unsigned long long accA[OUT_BLK], accB[OUT_BLK];
    #pragma unroll
    for (int o = 0; o < OUT_BLK; o++) { accA[o] = 0ull; accB[o] = 0ull; }

    {
        __syncthreads();
        for (int idx = tid; idx < CI_CHUNK * 324; idx += 256) {
            int ci = idx / 324;
            int rem = idx - ci * 324;
            int yy = rem / 18, xx = rem - yy * 18;
            int g = ci / CPREV;
            int cc = ci - g * CPREV;
            int gy = ty + yy - 1;
            if (gy < 0) gy += N;
            if (gy >= N) gy -= N;
            int gx = tx + xx - 1;
            if (gx < 0) gx += N;
            if (gx >= N) gx -= N;
            int sy = 2 * gy + (g & 1);
            int sx = 2 * gx + ((g ^ (g >> 1)) & 1);
            size_t base = ((size_t)cc * H + sy) * H + sx;
            size_t bstr = (size_t)CPREV * H * H;
            float4 val;
            val.x = X[base + (size_t)(b0 + 0) * bstr];
            val.y = X[base + (size_t)(b0 + 1) * bstr];
            val.z = X[base + (size_t)(b0 + 2) * bstr];
            val.w = X[base + (size_t)(b0 + 3) * bstr];
            *(float4*)(S + idx * 4) = val;
        }
        for (int idx = tid; idx < CI_CHUNK * 9 * OUT_BLK; idx += 256) {
            int ci = idx / (9 * OUT_BLK);
            int rem = idx - ci * 9 * OUT_BLK;
            int tap = rem / OUT_BLK;
            int o = rem - tap * OUT_BLK;
            float k = Kw[((size_t)o * CIN + ci) * 9 + tap];
            KS[idx] = make_float2(k, k);
        }
        __syncthreads();

        #pragma unroll 1
        for (int ci = 0; ci < CI_CHUNK; ci++) {
            const float* Sci = S + ci * 1296;
            const float2* Kci = KS + ci * 9 * OUT_BLK;
            #pragma unroll
            for (int tap = 0; tap < 9; tap++) {
                int dy = tap / 3, dx = tap - dy * 3;
                ulonglong2 v =
                    *(const ulonglong2*)(Sci + ((py + dy) * 18 + (px + dx)) * 4);
                #pragma unroll
                for (int o = 0; o < OUT_BLK; o += 2) {
                    ulonglong2 kk = *(const ulonglong2*)(Kci + tap * OUT_BLK + o);
                    ffma2(accA[o], kk.x, v.x);
                    ffma2(accB[o], kk.x, v.y);
                    ffma2(accA[o + 1], kk.y, v.x);
                    ffma2(accB[o + 1], kk.y, v.y);
                }
            }
        }
    }

    const int i = ty + py, j = tx + px;
    const int y = i >> 1, x = j >> 1;
    const int hs = i & 1, ws = j & 1;
    const int g = (hs == ws) ? hs : (2 + hs);
    const int p = y * 32 + x;
    float ld[4] = {0.f, 0.f, 0.f, 0.f};
    uint32_t pk[6][4];

    #pragma unroll
    for (int o = 0; o < OUT_BLK; o += 2) {
        float e0 = sE[o], a0v = sAb[o];
        float e1 = sE[o + 1], a1v = sAb[o + 1];
        float c0v = cb[((size_t)o * N + i) * N + j];
        float c1v = cb[((size_t)(o + 1) * N + i) * N + j];
        float2 pA0 = up2(accA[o]), pB0 = up2(accB[o]);
        float2 pA1 = up2(accA[o + 1]), pB1 = up2(accB[o + 1]);
        float z0[4] = {pA0.x, pA0.y, pB0.x, pB0.y};
        float z1[4] = {pA1.x, pA1.y, pB1.x, pB1.y};
        float t0[4], t1[4];
        #pragma unroll
        for (int nb = 0; nb < 4; nb++) {
            t0[nb] = tanhf((z0[nb] + c0v) * e0 + a0v);
            t1[nb] = tanhf((z1[nb] + c1v) * e1 + a1v);
            ld[nb] += log1pf(-t0[nb] * t0[nb]) + log1pf(-t1[nb] * t1[nb]);
            __nv_bfloat162 p2;
            p2.x = __float2bfloat16(t0[nb]);
            p2.y = __float2bfloat16(t1[nb]);
            pk[o >> 1][nb] = *(uint32_t*)&p2;
        }
        *(float4*)(Y + (((size_t)bq * 48 + g * 12 + o) * 1024 + p) * 4) =
            make_float4(t0[0], t0[1], t0[2], t0[3]);
        *(float4*)(Y + (((size_t)bq * 48 + g * 12 + o + 1) * 1024 + p) * 4) =
            make_float4(t1[0], t1[1], t1[2], t1[3]);
    }

    {
        #pragma unroll
        for (int nb = 0; nb < 4; nb++) {
            size_t base = ((size_t)(b0 + nb) * 1024 + p) * 64 + g * 12;
            *(uint2*)(YB + base) = make_uint2(pk[0][nb], pk[1][nb]);
            *(uint2*)(YB + base + 4) = make_uint2(pk[2][nb], pk[3][nb]);
            *(uint2*)(YB + base + 8) = make_uint2(pk[4][nb], pk[5][nb]);
        }
    }

    #pragma unroll
    for (int nb = 0; nb < 4; nb++) ld[nb] = wred(ld[nb]);
    __syncthreads();
    float* red = S;
    if ((tid & 31) == 0) {
        int w = tid >> 5;
        red[w * 4 + 0] = ld[0];
        red[w * 4 + 1] = ld[1];
        red[w * 4 + 2] = ld[2];
        red[w * 4 + 3] = ld[3];
    }
    __syncthreads();
    if (tid < 4) {
        float s = 0.f;
        #pragma unroll
        for (int w = 0; w < 8; w++) s += red[w * 4 + tid];
        atomicAdd(&g_tld[b0 + tid], s);
    }
}

// ---------------- layer 1: HMMA, single-stage smem (R12, verified) ----------
#define L1_WT_BASE 40960
#define L1_SMEM 114688

__global__ void __launch_bounds__(256, 2)
l1_mma(const __nv_bfloat16* __restrict__ ag, const float* __restrict__ x1p,
       const float* __restrict__ cb, const float* __restrict__ ab,
       const float* __restrict__ als,
       __nv_bfloat16* __restrict__ xg, float* __restrict__ xf) {
    extern __shared__ char smc[];
    __shared__ float sE[48], sAb[48], red[8];
    uint32_t smem_base = smem_u32(smc);
    const int tid = threadIdx.x;
    const int lane = tid & 31, wid = tid >> 5;
    const int b = blockIdx.x;
    const int mt0 = blockIdx.y * 256;
    const int ytile0 = mt0 >> 5;
    const int m0 = (wid & 3) * 64;
    const int n0 = (wid >> 2) * 32;
    const int bq = b >> 2, nb = b & 3;

    if (tid < 48) {
        sE[tid] = expf(als[tid]);
        sAb[tid] = ab[tid];
    }

    for (int r = tid; r < 320; r += 256) {
        int yrel = r >> 5, x = r & 31;
        int yg = (ytile0 - 1 + yrel) & 31;
        const char* src = (const char*)(ag + ((size_t)b * 1024 + yg * 32 + x) * 64);
        #pragma unroll
        for (int s = 0; s < 8; s++) {
            uint32_t off = (uint32_t)r * 128 + s * 16;
            cpasync16(smem_base + swz(off), src + s * 16);
        }
    }
    for (int r = tid; r < 576; r += 256) {
        const char* src = (const char*)(g_w1 + (size_t)r * 64);
        #pragma unroll
        for (int s = 0; s < 8; s++) {
            uint32_t off = (uint32_t)r * 128 + s * 16;
            cpasync16(smem_base + L1_WT_BASE + swz(off), src + s * 16);
        }
    }
    cpasync_commit();

    float d[4][4][4];
    #pragma unroll
    for (int mt = 0; mt < 4; mt++)
        #pragma unroll
        for (int nt = 0; nt < 4; nt++)
            #pragma unroll
            for (int r = 0; r < 4; r++) d[mt][nt][r] = 0.f;

    int ply[4], plx[4];
    #pragma unroll
    for (int mt = 0; mt < 4; mt++) {
        int pl = m0 + mt * 16 + (lane & 15);
        ply[mt] = pl >> 5;
        plx[mt] = pl & 31;
    }

    cpasync_wait<0>();
    __syncthreads();

    #pragma unroll 1
    for (int c = 0; c < 9; c++) {
        int dy = c / 3 - 1, dx = c % 3 - 1;
        #pragma unroll
        for (int ks = 0; ks < 4; ks++) {
            uint32_t a[4][4];
            #pragma unroll
            for (int mt = 0; mt < 4; mt++) {
                int row = (ply[mt] + 1 + dy) * 32 + ((plx[mt] + dx) & 31);
                uint32_t off = (uint32_t)row * 128 + ks * 32 + (lane >> 4) * 16;
                ldsm4(a[mt], smem_base + swz(off));
            }
            uint32_t bf[2][4];
            #pragma unroll
            for (int nh = 0; nh < 2; nh++) {
                uint32_t row = c * 64 + n0 + nh * 16 + (lane & 7) + ((lane >> 4) << 3);
                uint32_t off = row * 128 + ks * 32 + ((lane >> 3) & 1) * 16;
                ldsm4(bf[nh], smem_base + L1_WT_BASE + swz(off));
            }
            #pragma unroll
            for (int mt = 0; mt < 4; mt++)
                #pragma unroll
                for (int nt = 0; nt < 4; nt++)
                    mma16816(d[mt][nt], a[mt], &bf[nt >> 1][(nt & 1) * 2]);
        }
    }

    // epilogue: center add (squeezed-co x1sq, direct index) + cb + actnorm + tanh
    float ldsum = 0.f;
    #pragma unroll
    for (int nt = 0; nt < 4; nt++) {
        int co = n0 + nt * 8 + (lane & 3) * 2;
        if (co < 48) {
            float e0 = sE[co], e1 = sE[co + 1];
            float ab0 = sAb[co], ab1 = sAb[co + 1];
            const float* xc0p = x1p + ((size_t)bq * 48 + co) * 4096 + nb;
            const float* xc1p = x1p + ((size_t)bq * 48 + co + 1) * 4096 + nb;
            #pragma unroll
            for (int mt = 0; mt < 4; mt++) {
                #pragma unroll
                for (int half = 0; half < 2; half++) {
                    int p = mt0 + m0 + mt * 16 + (lane >> 2) + half * 8;
                    float xc0 = xc0p[p * 4];
                    float xc1 = xc1p[p * 4];
                    float z0 = d[mt][nt][half * 2] + xc0 + cb[(size_t)co * 1024 + p];
                    float z1 = d[mt][nt][half * 2 + 1] + xc1 + cb[(size_t)(co + 1) * 1024 + p];
                    float t0 = tanhf(z0 * e0 + ab0);
                    float t1 = tanhf(z1 * e1 + ab1);
                    ldsum += log1pf(-t0 * t0) + log1pf(-t1 * t1);
                    int i = p >> 5, j = p & 31;
                    int y = i >> 1, x = j >> 1;
                    int hs = i & 1, ws = j & 1;
                    int g = (hs == ws) ? hs : (2 + hs);
                    size_t xi = ((size_t)b * 256 + y * 16 + x) * 192 + g * 48 + co;
                    __nv_bfloat162 pk2;
                    pk2.x = __float2bfloat16(t0);
                    pk2.y = __float2bfloat16(t1);
                    *(__nv_bfloat162*)(xg + xi) = pk2;
                    *(float2*)(xf + xi) = make_float2(t0, t1);
                }
            }
        }
    }
    ldsum = wred(ldsum);
    if (lane == 0) red[wid] = ldsum;
    __syncthreads();
    if (tid == 0) {
        float s = 0.f;
        #pragma unroll
        for (int w = 0; w < 8; w++) s += red[w];
        atomicAdd(&g_tld[b], s);
    }
}

// ---------------- layer 2: HMMA, act slabs once + dbuf weights (R12) ---------
#define L2_WT_BASE 98304
#define L2_SMEM 114688

__device__ __forceinline__ void l2_stage_wt(uint32_t smem_base, int buf, int c,
                                            int co0, int tid) {
    const char* wbase = (const char*)(g_w2 + ((size_t)c * 192 + co0) * 64);
    uint32_t ra = smem_base + L2_WT_BASE + buf * 8192;
    #pragma unroll
    for (int s2 = tid; s2 < 512; s2 += 256) {
        uint32_t off = (uint32_t)s2 * 16;
        cpasync16(ra + swz(off), wbase + off);
    }
    cpasync_commit();
}

__global__ void __launch_bounds__(256, 2)
l2_mma(const __nv_bfloat16* __restrict__ xg, const float* __restrict__ xf,
       const float* __restrict__ cb, const float* __restrict__ ab,
       const float* __restrict__ als, float* __restrict__ out) {
    extern __shared__ char smc[];
    __shared__ float sE[64], sAb[64];
    uint32_t smem_base = smem_u32(smc);
    const int tid = threadIdx.x;
    const int lane = tid & 31, wid = tid >> 5;
    const int b = blockIdx.x;
    const int co0 = blockIdx.y * 64;
    const int m0 = (wid & 3) * 64;
    const int n0 = (wid >> 2) * 32;

    if (tid < 64) {
        sE[tid] = expf(als[co0 + tid]);
        sAb[tid] = ab[co0 + tid];
    }

    for (int r = tid; r < 768; r += 256) {
        int cc = r >> 8, p = r & 255;
        const char* src = (const char*)(xg + ((size_t)b * 256 + p) * 192 + cc * 64);
        uint32_t base = smem_base + cc * 32768;
        #pragma unroll
        for (int s = 0; s < 8; s++) {
            uint32_t off = (uint32_t)p * 128 + s * 16;
            cpasync16(base + swz(off), src + s * 16);
        }
    }
    l2_stage_wt(smem_base, 0, 0, co0, tid);

    float d[4][4][4];
    #pragma unroll
    for (int mt = 0; mt < 4; mt++)
        #pragma unroll
        for (int nt = 0; nt < 4; nt++)
            #pragma unroll
            for (int r = 0; r < 4; r++) d[mt][nt][r] = 0.f;

    int ply[4], plx[4];
    #pragma unroll
    for (int mt = 0; mt < 4; mt++) {
        int pl = m0 + mt * 16 + (lane & 15);
        ply[mt] = pl >> 4;
        plx[mt] = pl & 15;
    }

    #pragma unroll 1
    for (int c = 0; c < 27; c++) {
        int cur = c & 1;
        cpasync_wait<0>();
        __syncthreads();
        if (c + 1 < 27) l2_stage_wt(smem_base, 1 - cur, c + 1, co0, tid);
        int tap = c / 3, cc = c - tap * 3;
        int dy = tap / 3 - 1, dx = tap % 3 - 1;
        uint32_t actb = smem_base + cc * 32768;
        uint32_t wtb = smem_base + L2_WT_BASE + cur * 8192;
        #pragma unroll
        for (int ks = 0; ks < 4; ks++) {
            uint32_t a[4][4];
            #pragma unroll
            for (int mt = 0; mt < 4; mt++) {
                int row = ((ply[mt] + dy) & 15) * 16 + ((plx[mt] + dx) & 15);
                uint32_t off = (uint32_t)row * 128 + ks * 32 + (lane >> 4) * 16;
                ldsm4(a[mt], actb + swz(off));
            }
            uint32_t bf[2][4];
            #pragma unroll
            for (int nh = 0; nh < 2; nh++) {
                uint32_t row = n0 + nh * 16 + (lane & 7) + ((lane >> 4) << 3);
                uint32_t off = row * 128 + ks * 32 + ((lane >> 3) & 1) * 16;
                ldsm4(bf[nh], wtb + swz(off));
            }
            #pragma unroll
            for (int mt = 0; mt < 4; mt++)
                #pragma unroll
                for (int nt = 0; nt < 4; nt++)
                    mma16816(d[mt][nt], a[mt], &bf[nt >> 1][(nt & 1) * 2]);
        }
    }

    #pragma unroll
    for (int nt = 0; nt < 4; nt++) {
        int cr = n0 + nt * 8 + (lane & 3) * 2;
        int co = co0 + cr;
        float e0 = sE[cr], e1 = sE[cr + 1];
        float ab0 = sAb[cr], ab1 = sAb[cr + 1];
        const float* cb0p = cb + (size_t)co * 256;
        const float* cb1p = cb + (size_t)(co + 1) * 256;
        float* o0p = out + ((size_t)b * 192 + co) * 256;
        float* o1p = out + ((size_t)b * 192 + co + 1) * 256;
        #pragma unroll
        for (int mt = 0; mt < 4; mt++) {
            int p = m0 + mt * 16 + (lane >> 2);
            const float* xf0 = xf + ((size_t)b * 256 + p) * 192;
            const float* xf8 = xf + ((size_t)b * 256 + p + 8) * 192;
            o0p[p] = (d[mt][nt][0] + xf0[co] + cb0p[p]) * e0 + ab0;
            o1p[p] = (d[mt][nt][1] + xf0[co + 1] + cb1p[p]) * e1 + ab1;
            o0p[p + 8] = (d[mt][nt][2] + xf8[co] + cb0p[p + 8]) * e0 + ab0;
            o1p[p + 8] = (d[mt][nt][3] + xf8[co + 1] + cb1p[p + 8]) * e1 + ab1;
        }
    }
}

// ---------------- launch ----------------
extern "C" void kernel_launch(void* const* d_in, const int* in_sizes, int n_in,
                              void* d_out, int out_size) {
    const float* x = (const float*)d_in[0];
    const float* k0 = (const float*)d_in[1];
    const float* cb0 = (const float*)d_in[2];
    const float* ab0 = (const float*)d_in[3];
    const float* als0 = (const float*)d_in[4];
    const float* k1 = (const float*)d_in[5];
    const float* cb1 = (const float*)d_in[6];
    const float* ab1 = (const float*)d_in[7];
    const float* als1 = (const float*)d_in[8];
    const float* k2 = (const float*)d_in[9];
    const float* cb2 = (const float*)d_in[10];
    const float* ab2 = (const float*)d_in[11];
    const float* als2 = (const float*)d_in[12];
    float* out = (float*)d_out;

    float *x1, *xf;
    __nv_bfloat16 *ag1, *xg;
    cudaGetSymbolAddress((void**)&x1, g_x1);
    cudaGetSymbolAddress((void**)&ag1, g_ag1);
    cudaGetSymbolAddress((void**)&xg, g_xg);
    cudaGetSymbolAddress((void**)&xf, g_xf32);

    const int SM0 = 12 * 324 * 4 * 4 + 12 * 9 * 12 * 8 + 12 * 2 * 4;
    cudaFuncSetAttribute((const void*)conv_layer0,
                         cudaFuncAttributeMaxDynamicSharedMemorySize, SM0);
    cudaFuncSetAttribute((const void*)l1_mma,
                         cudaFuncAttributeMaxDynamicSharedMemorySize, L1_SMEM);
    cudaFuncSetAttribute((const void*)l2_mma,
                         cudaFuncAttributeMaxDynamicSharedMemorySize, L2_SMEM);

    setup_kernel<<<2483, 256>>>(k0, k1, k2);
    conv_layer0<<<dim3(64, 16, 1), 256, SM0>>>(x, k0, cb0, ab0, als0, x1, ag1);
    l1_mma<<<dim3(256, 4), 256, L1_SMEM>>>(ag1, x1, cb1, ab1, als1, xg, xf);
    l2_mma<<<dim3(256, 3), 256, L2_SMEM>>>(xg, xf, cb2, ab2, als2, out);
    fin_kernel<<<1, 256>>>(als0, als1, als2, out);
}

// round 15
// speedup vs baseline: 1.0693x; 1.0246x over previous
#include <cuda_runtime.h>
#include <cuda_bf16.h>
#include <cstdint>

// ---------------- device scratch (no allocations allowed) ----------------
__device__ __align__(16) float g_x1[256 * 12 * 64 * 64];          // L0 out squeezed-co fp32 [bq][48][1024][4]
__device__ __align__(16) __nv_bfloat16 g_ag1[256 * 1024 * 64];    // L0 out squeezed bf16 [b][p][ci(48,pad64)]
__device__ __align__(16) __nv_bfloat16 g_w1[9 * 64 * 64];         // L1 residual weights (K1 - I) bf16, padded
__device__ __align__(16) __nv_bfloat16 g_xg[256 * 256 * 192];     // L2 input bf16 [b][p][ci]
__device__ __align__(16) float g_xf32[256 * 256 * 192];           // same, fp32 (L2 center add) [b][p][ci]
__device__ __align__(16) __nv_bfloat16 g_w2[9 * 3 * 192 * 64];    // L2 residual weights (K2 - I) bf16
__device__ float g_tld[256];
__device__ float g_trT[3][9];
__device__ float g_trS[3][81];
__device__ float g_t2p[16][9];
__device__ float g_s2p[16][81];

#define X_ELEMS (256 * 192 * 16 * 16)

// ---------------- packed f32x2 helpers ----------------
__device__ __forceinline__ void ffma2(unsigned long long& d, unsigned long long a,
                                      unsigned long long b) {
    asm("fma.rn.f32x2 %0, %1, %2, %0;" : "+l"(d) : "l"(a), "l"(b));
}
__device__ __forceinline__ float2 up2(unsigned long long v) {
    float2 f;
    asm("mov.b64 {%0,%1}, %2;" : "=f"(f.x), "=f"(f.y) : "l"(v));
    return f;
}
__device__ __forceinline__ float wred(float v) {
    #pragma unroll
    for (int o = 16; o; o >>= 1) v += __shfl_xor_sync(0xffffffffu, v, o);
    return v;
}

// ---------------- PTX helpers ----------------
__device__ __forceinline__ uint32_t smem_u32(const void* p) {
    uint32_t a;
    asm("{ .reg .u64 t; cvta.to.shared.u64 t, %1; cvt.u32.u64 %0, t; }" : "=r"(a) : "l"(p));
    return a;
}
__device__ __forceinline__ void cpasync16(uint32_t dst, const void* src) {
    asm volatile("cp.async.cg.shared.global [%0], [%1], 16;" :: "r"(dst), "l"(src));
}
__device__ __forceinline__ void cpasync_commit() {
    asm volatile("cp.async.commit_group;" ::: "memory");
}
template <int N>
__device__ __forceinline__ void cpasync_wait() {
    asm volatile("cp.async.wait_group %0;" :: "n"(N) : "memory");
}
__device__ __forceinline__ void ldsm4(uint32_t* r, uint32_t addr) {
    asm volatile("ldmatrix.sync.aligned.m8n8.x4.shared.b16 {%0,%1,%2,%3}, [%4];"
                 : "=r"(r[0]), "=r"(r[1]), "=r"(r[2]), "=r"(r[3]) : "r"(addr));
}
__device__ __forceinline__ void mma16816(float* d, const uint32_t* a, const uint32_t* b) {
    asm volatile(
        "mma.sync.aligned.m16n8k16.row.col.f32.bf16.bf16.f32 "
        "{%0,%1,%2,%3}, {%4,%5,%6,%7}, {%8,%9}, {%0,%1,%2,%3};"
        : "+f"(d[0]), "+f"(d[1]), "+f"(d[2]), "+f"(d[3])
        : "r"(a[0]), "r"(a[1]), "r"(a[2]), "r"(a[3]), "r"(b[0]), "r"(b[1]));
}
__device__ __forceinline__ uint32_t swz(uint32_t off) { return off ^ ((off >> 3) & 0x70); }

// ---------------- trace accumulation (partial pair range) ----------------
__device__ void trace_accum(const float* __restrict__ K, int c, int lo, int hi,
                            float* __restrict__ gT, float* __restrict__ gS) {
    __shared__ float shS[81];
    __shared__ float shT[9];
    const int tid = threadIdx.x;
    if (tid < 81) shS[tid] = 0.f;
    if (tid < 9) shT[tid] = 0.f;
    __syncthreads();
    float a81[81], t9[9];
    #pragma unroll
    for (int k = 0; k < 81; k++) a81[k] = 0.f;
    #pragma unroll
    for (int k = 0; k < 9; k++) t9[k] = 0.f;
    for (int idx = lo + tid; idx < hi; idx += 256) {
        int i = idx / c, j = idx - i * c;
        const float* Ka = K + (size_t)(i * c + j) * 9;
        const float* Kb = K + (size_t)(j * c + i) * 9;
        float av[9], bv[9];
        #pragma unroll
        for (int a = 0; a < 9; a++) { av[a] = Ka[a]; bv[a] = Kb[a]; }
        #pragma unroll
        for (int a = 0; a < 9; a++)
            #pragma unroll
            for (int b = 0; b < 9; b++) a81[a * 9 + b] += av[a] * bv[b];
        if (i == j) {
            #pragma unroll
            for (int a = 0; a < 9; a++) t9[a] += av[a];
        }
    }
    #pragma unroll
    for (int k = 0; k < 81; k++) atomicAdd(&shS[k], a81[k]);
    #pragma unroll
    for (int k = 0; k < 9; k++) atomicAdd(&shT[k], t9[k]);
    __syncthreads();
    if (tid < 81) gS[tid] = shS[tid];
    if (tid < 9) gT[tid] = shT[tid];
}

// ---------------- fused setup ----------------
__global__ void setup_kernel(const float* __restrict__ K0, const float* __restrict__ K1,
                             const float* __restrict__ K2) {
    int bid = blockIdx.x, tid = threadIdx.x;
    if (bid == 0) {
        g_tld[tid] = 0.f;
    } else if (bid <= 1024) {
        int idx = (bid - 1) * 256 + tid;
        uint4 z = make_uint4(0, 0, 0, 0);
        *(uint4*)(g_ag1 + (size_t)idx * 64 + 48) = z;
        *(uint4*)(g_ag1 + (size_t)idx * 64 + 56) = z;
    } else if (bid <= 1168) {
        int idx = (bid - 1025) * 256 + tid;
        int cil = idx & 63;
        int r = idx >> 6;
        int co = r % 64;
        int tap = r / 64;
        float w = 0.f;
        if (co < 48 && cil < 48) {
            w = K1[((size_t)co * 48 + cil) * 9 + tap];
            if (tap == 4 && cil == co) w -= 1.0f;
        }
        g_w1[idx] = __float2bfloat16(w);
    } else if (bid <= 2464) {
        int idx = (bid - 1169) * 256 + tid;
        int cil = idx & 63;
        int r = idx >> 6;
        int co = r % 192;
        int q = r / 192;
        int cc = q % 3;
        int tap = q / 3;
        int ci = cc * 64 + cil;
        float w = K2[((size_t)co * 192 + ci) * 9 + tap];
        if (tap == 4 && ci == co) w -= 1.0f;
        g_w2[idx] = __float2bfloat16(w);
    } else if (bid == 2465) {
        trace_accum(K0, 12, 0, 144, g_trT[0], g_trS[0]);
    } else if (bid == 2466) {
        trace_accum(K1, 48, 0, 2304, g_trT[1], g_trS[1]);
    } else {
        int blk = bid - 2467;
        trace_accum(K2, 192, blk * 2304, (blk + 1) * 2304, g_t2p[blk], g_s2p[blk]);
    }
}

// ---------------- finalize ----------------
__device__ __forceinline__ float2 cmul(float2 a, float2 b) {
    return make_float2(a.x * b.x - a.y * b.y, a.x * b.y + a.y * b.x);
}

__global__ void fin_kernel(const float* __restrict__ a0, const float* __restrict__ a1,
                           const float* __restrict__ a2, float* __restrict__ out) {
    __shared__ float shT[9], shS[81], red[8];
    __shared__ float stot;
    const int tid = threadIdx.x;
    float part = 0.f;
    #pragma unroll 1
    for (int L = 0; L < 3; L++) {
        const float* als = (L == 0) ? a0 : ((L == 1) ? a1 : a2);
        const int c = (L == 0) ? 12 : ((L == 1) ? 48 : 192);
        const int n = (L == 0) ? 64 : ((L == 1) ? 32 : 16);
        __syncthreads();
        if (tid < 9) {
            float s;
            if (L < 2) s = g_trT[L][tid];
            else {
                s = 0.f;
                #pragma unroll
                for (int p = 0; p < 16; p++) s += g_t2p[p][tid];
            }
            shT[tid] = s;
        }
        if (tid < 81) {
            float s;
            if (L < 2) s = g_trS[L][tid];
            else {
                s = 0.f;
                #pragma unroll
                for (int p = 0; p < 16; p++) s += g_s2p[p][tid];
            }
            shS[tid] = s;
        }
        __syncthreads();
        for (int f = tid; f < n * n; f += 256) {
            int u = f / n, v = f - u * n;
            float su, cu, sv, cv;
            sincosf(-6.283185307179586f * (float)u / (float)n, &su, &cu);
            sincosf(-6.283185307179586f * (float)v / (float)n, &sv, &cv);
            float2 eu = make_float2(cu, su), ev = make_float2(cv, sv);
            float2 pU[3] = {make_float2(1.f, 0.f), eu, cmul(eu, eu)};
            float2 pV[3] = {make_float2(1.f, 0.f), ev, cmul(ev, ev)};
            float2 ph[9];
            #pragma unroll
            for (int dy = 0; dy < 3; dy++)
                #pragma unroll
                for (int dx = 0; dx < 3; dx++) ph[dy * 3 + dx] = cmul(pU[dy], pV[dx]);
            float2 T = make_float2(0.f, 0.f), T2 = make_float2(0.f, 0.f);
            #pragma unroll
            for (int a = 0; a < 9; a++) {
                T.x += shT[a] * ph[a].x;
                T.y += shT[a] * ph[a].y;
            }
            #pragma unroll
            for (int a = 0; a < 9; a++) {
                float2 inner = make_float2(0.f, 0.f);
                #pragma unroll
                for (int b = 0; b < 9; b++) {
                    float s = shS[a * 9 + b];
                    inner.x += s * ph[b].x;
                    inner.y += s * ph[b].y;
                }
                float2 pi = cmul(ph[a], inner);
                T2.x += pi.x;
                T2.y += pi.y;
            }
            float2 e1 = cmul(pU[1], pV[1]);
            e1.y = -e1.y;
            float2 e2 = cmul(e1, e1);
            float A = e1.x * T.x - e1.y * T.y;
            float B = e2.x * T2.x - e2.y * T2.y;
            part += 2.f * A - 1.5f * (float)c - 0.5f * B;
        }
        float as = 0.f;
        for (int k = tid; k < c; k += 256) as += als[k];
        part += (float)(n * n) * as;
    }
    float w = wred(part);
    if ((tid & 31) == 0) red[tid >> 5] = w;
    __syncthreads();
    if (tid == 0) {
        float s = 0.f;
        #pragma unroll
        for (int q = 0; q < 8; q++) s += red[q];
        stot = s;
    }
    __syncthreads();
    out[X_ELEMS + tid] = stot + g_tld[tid];
}

// ---------------- layer 0: fused FFMA conv (R12 exact, 2 CTAs/SM) ------------
__global__ void __launch_bounds__(256, 2)
conv_layer0(const float* __restrict__ X, const float* __restrict__ Kw,
            const float* __restrict__ cb, const float* __restrict__ ab,
            const float* __restrict__ als, float* __restrict__ Y,
            __nv_bfloat16* __restrict__ YB) {
    constexpr int CPREV = 3, N = 64, CI_CHUNK = 12, OUT_BLK = 12;
    constexpr int CIN = 12, H = 128;
    constexpr int S_FLOATS = CI_CHUNK * 324 * 4;
    extern __shared__ float smem[];
    float* S = smem;
    float2* KS = (float2*)(smem + S_FLOATS);
    float* sE = (float*)(KS + CI_CHUNK * 9 * OUT_BLK);
    float* sAb = sE + OUT_BLK;

    const int tid = threadIdx.x;
    const int bq = blockIdx.x;
    const int b0 = bq * 4;
    constexpr int TILES_X = N / 16;
    const int ty = (blockIdx.y / TILES_X) * 16;
    const int tx = (blockIdx.y % TILES_X) * 16;
    const int py = tid >> 4, px = tid & 15;

    if (tid < OUT_BLK) {
        sE[tid] = expf(als[tid]);
        sAb[tid] = ab[tid];
    }

    unsigned long long accA[OUT_BLK], accB[OUT_BLK];
    #pragma unroll
    for (int o = 0; o < OUT_BLK; o++) { accA[o] = 0ull; accB[o] = 0ull; }

    {
        __syncthreads();
        for (int idx = tid; idx < CI_CHUNK * 324; idx += 256) {
            int ci = idx / 324;
            int rem = idx - ci * 324;
            int yy = rem / 18, xx = rem - yy * 18;
            int g = ci / CPREV;
            int cc = ci - g * CPREV;
            int gy = ty + yy - 1;
            if (gy < 0) gy += N;
            if (gy >= N) gy -= N;
            int gx = tx + xx - 1;
            if (gx < 0) gx += N;
            if (gx >= N) gx -= N;
            int sy = 2 * gy + (g & 1);
            int sx = 2 * gx + ((g ^ (g >> 1)) & 1);
            size_t base = ((size_t)cc * H + sy) * H + sx;
            size_t bstr = (size_t)CPREV * H * H;
            float4 val;
            val.x = X[base + (size_t)(b0 + 0) * bstr];
            val.y = X[base + (size_t)(b0 + 1) * bstr];
            val.z = X[base + (size_t)(b0 + 2) * bstr];
            val.w = X[base + (size_t)(b0 + 3) * bstr];
            *(float4*)(S + idx * 4) = val;
        }
        for (int idx = tid; idx < CI_CHUNK * 9 * OUT_BLK; idx += 256) {
            int ci = idx / (9 * OUT_BLK);
            int rem = idx - ci * 9 * OUT_BLK;
            int tap = rem / OUT_BLK;
            int o = rem - tap * OUT_BLK;
            float k = Kw[((size_t)o * CIN + ci) * 9 + tap];
            KS[idx] = make_float2(k, k);
        }
        __syncthreads();

        #pragma unroll 1
        for (int ci = 0; ci < CI_CHUNK; ci++) {
            const float* Sci = S + ci * 1296;
            const float2* Kci = KS + ci * 9 * OUT_BLK;
            #pragma unroll
            for (int tap = 0; tap < 9; tap++) {
                int dy = tap / 3, dx = tap - dy * 3;
                ulonglong2 v =
                    *(const ulonglong2*)(Sci + ((py + dy) * 18 + (px + dx)) * 4);
                #pragma unroll
                for (int o = 0; o < OUT_BLK; o += 2) {
                    ulonglong2 kk = *(const ulonglong2*)(Kci + tap * OUT_BLK + o);
                    ffma2(accA[o], kk.x, v.x);
                    ffma2(accB[o], kk.x, v.y);
                    ffma2(accA[o + 1], kk.y, v.x);
                    ffma2(accB[o + 1], kk.y, v.y);
                }
            }
        }
    }

    const int i = ty + py, j = tx + px;
    const int y = i >> 1, x = j >> 1;
    const int hs = i & 1, ws = j & 1;
    const int g = (hs == ws) ? hs : (2 + hs);
    const int p = y * 32 + x;
    float ld[4] = {0.f, 0.f, 0.f, 0.f};
    uint32_t pk[6][4];

    #pragma unroll
    for (int o = 0; o < OUT_BLK; o += 2) {
        float e0 = sE[o], a0v = sAb[o];
        float e1 = sE[o + 1], a1v = sAb[o + 1];
        float c0v = cb[((size_t)o * N + i) * N + j];
        float c1v = cb[((size_t)(o + 1) * N + i) * N + j];
        float2 pA0 = up2(accA[o]), pB0 = up2(accB[o]);
        float2 pA1 = up2(accA[o + 1]), pB1 = up2(accB[o + 1]);
        float z0[4] = {pA0.x, pA0.y, pB0.x, pB0.y};
        float z1[4] = {pA1.x, pA1.y, pB1.x, pB1.y};
        float t0[4], t1[4];
        #pragma unroll
        for (int nb = 0; nb < 4; nb++) {
            t0[nb] = tanhf((z0[nb] + c0v) * e0 + a0v);
            t1[nb] = tanhf((z1[nb] + c1v) * e1 + a1v);
            ld[nb] += log1pf(-t0[nb] * t0[nb]) + log1pf(-t1[nb] * t1[nb]);
            __nv_bfloat162 p2;
            p2.x = __float2bfloat16(t0[nb]);
            p2.y = __float2bfloat16(t1[nb]);
            pk[o >> 1][nb] = *(uint32_t*)&p2;
        }
        *(float4*)(Y + (((size_t)bq * 48 + g * 12 + o) * 1024 + p) * 4) =
            make_float4(t0[0], t0[1], t0[2], t0[3]);
        *(float4*)(Y + (((size_t)bq * 48 + g * 12 + o + 1) * 1024 + p) * 4) =
            make_float4(t1[0], t1[1], t1[2], t1[3]);
    }

    {
        #pragma unroll
        for (int nb = 0; nb < 4; nb++) {
            size_t base = ((size_t)(b0 + nb) * 1024 + p) * 64 + g * 12;
            *(uint2*)(YB + base) = make_uint2(pk[0][nb], pk[1][nb]);
            *(uint2*)(YB + base + 4) = make_uint2(pk[2][nb], pk[3][nb]);
            *(uint2*)(YB + base + 8) = make_uint2(pk[4][nb], pk[5][nb]);
        }
    }

    #pragma unroll
    for (int nb = 0; nb < 4; nb++) ld[nb] = wred(ld[nb]);
    __syncthreads();
    float* red = S;
    if ((tid & 31) == 0) {
        int w = tid >> 5;
        red[w * 4 + 0] = ld[0];
        red[w * 4 + 1] = ld[1];
        red[w * 4 + 2] = ld[2];
        red[w * 4 + 3] = ld[3];
    }
    __syncthreads();
    if (tid < 4) {
        float s = 0.f;
        #pragma unroll
        for (int w = 0; w < 8; w++) s += red[w * 4 + tid];
        atomicAdd(&g_tld[b0 + tid], s);
    }
}

// ---------------- layer 1: HMMA, single-stage smem (R12 exact) ----------
#define L1_WT_BASE 40960
#define L1_SMEM 114688

__global__ void __launch_bounds__(256, 2)
l1_mma(const __nv_bfloat16* __restrict__ ag, const float* __restrict__ x1p,
       const float* __restrict__ cb, const float* __restrict__ ab,
       const float* __restrict__ als,
       __nv_bfloat16* __restrict__ xg, float* __restrict__ xf) {
    extern __shared__ char smc[];
    __shared__ float sE[48], sAb[48], red[8];
    uint32_t smem_base = smem_u32(smc);
    const int tid = threadIdx.x;
    const int lane = tid & 31, wid = tid >> 5;
    const int b = blockIdx.x;
    const int mt0 = blockIdx.y * 256;
    const int ytile0 = mt0 >> 5;
    const int m0 = (wid & 3) * 64;
    const int n0 = (wid >> 2) * 32;
    const int bq = b >> 2, nb = b & 3;

    if (tid < 48) {
        sE[tid] = expf(als[tid]);
        sAb[tid] = ab[tid];
    }

    for (int r = tid; r < 320; r += 256) {
        int yrel = r >> 5, x = r & 31;
        int yg = (ytile0 - 1 + yrel) & 31;
        const char* src = (const char*)(ag + ((size_t)b * 1024 + yg * 32 + x) * 64);
        #pragma unroll
        for (int s = 0; s < 8; s++) {
            uint32_t off = (uint32_t)r * 128 + s * 16;
            cpasync16(smem_base + swz(off), src + s * 16);
        }
    }
    for (int r = tid; r < 576; r += 256) {
        const char* src = (const char*)(g_w1 + (size_t)r * 64);
        #pragma unroll
        for (int s = 0; s < 8; s++) {
            uint32_t off = (uint32_t)r * 128 + s * 16;
            cpasync16(smem_base + L1_WT_BASE + swz(off), src + s * 16);
        }
    }
    cpasync_commit();

    float d[4][4][4];
    #pragma unroll
    for (int mt = 0; mt < 4; mt++)
        #pragma unroll
        for (int nt = 0; nt < 4; nt++)
            #pragma unroll
            for (int r = 0; r < 4; r++) d[mt][nt][r] = 0.f;

    int ply[4], plx[4];
    #pragma unroll
    for (int mt = 0; mt < 4; mt++) {
        int pl = m0 + mt * 16 + (lane & 15);
        ply[mt] = pl >> 5;
        plx[mt] = pl & 31;
    }

    cpasync_wait<0>();
    __syncthreads();

    #pragma unroll 1
    for (int c = 0; c < 9; c++) {
        int dy = c / 3 - 1, dx = c % 3 - 1;
        #pragma unroll
        for (int ks = 0; ks < 4; ks++) {
            uint32_t a[4][4];
            #pragma unroll
            for (int mt = 0; mt < 4; mt++) {
                int row = (ply[mt] + 1 + dy) * 32 + ((plx[mt] + dx) & 31);
                uint32_t off = (uint32_t)row * 128 + ks * 32 + (lane >> 4) * 16;
                ldsm4(a[mt], smem_base + swz(off));
            }
            uint32_t bf[2][4];
            #pragma unroll
            for (int nh = 0; nh < 2; nh++) {
                uint32_t row = c * 64 + n0 + nh * 16 + (lane & 7) + ((lane >> 4) << 3);
                uint32_t off = row * 128 + ks * 32 + ((lane >> 3) & 1) * 16;
                ldsm4(bf[nh], smem_base + L1_WT_BASE + swz(off));
            }
            #pragma unroll
            for (int mt = 0; mt < 4; mt++)
                #pragma unroll
                for (int nt = 0; nt < 4; nt++)
                    mma16816(d[mt][nt], a[mt], &bf[nt >> 1][(nt & 1) * 2]);
        }
    }

    float ldsum = 0.f;
    #pragma unroll
    for (int nt = 0; nt < 4; nt++) {
        int co = n0 + nt * 8 + (lane & 3) * 2;
        if (co < 48) {
            float e0 = sE[co], e1 = sE[co + 1];
            float ab0 = sAb[co], ab1 = sAb[co + 1];
            const float* xc0p = x1p + ((size_t)bq * 48 + co) * 4096 + nb;
            const float* xc1p = x1p + ((size_t)bq * 48 + co + 1) * 4096 + nb;
            #pragma unroll
            for (int mt = 0; mt < 4; mt++) {
                #pragma unroll
                for (int half = 0; half < 2; half++) {
                    int p = mt0 + m0 + mt * 16 + (lane >> 2) + half * 8;
                    float xc0 = xc0p[p * 4];
                    float xc1 = xc1p[p * 4];
                    float z0 = d[mt][nt][half * 2] + xc0 + cb[(size_t)co * 1024 + p];
                    float z1 = d[mt][nt][half * 2 + 1] + xc1 + cb[(size_t)(co + 1) * 1024 + p];
                    float t0 = tanhf(z0 * e0 + ab0);
                    float t1 = tanhf(z1 * e1 + ab1);
                    ldsum += log1pf(-t0 * t0) + log1pf(-t1 * t1);
                    int i = p >> 5, j = p & 31;
                    int y = i >> 1, x = j >> 1;
                    int hs = i & 1, ws = j & 1;
                    int g = (hs == ws) ? hs : (2 + hs);
                    size_t xi = ((size_t)b * 256 + y * 16 + x) * 192 + g * 48 + co;
                    __nv_bfloat162 pk2;
                    pk2.x = __float2bfloat16(t0);
                    pk2.y = __float2bfloat16(t1);
                    *(__nv_bfloat162*)(xg + xi) = pk2;
                    *(float2*)(xf + xi) = make_float2(t0, t1);
                }
            }
        }
    }
    ldsum = wred(ldsum);
    if (lane == 0) red[wid] = ldsum;
    __syncthreads();
    if (tid == 0) {
        float s = 0.f;
        #pragma unroll
        for (int w = 0; w < 8; w++) s += red[w];
        atomicAdd(&g_tld[b], s);
    }
}

// ---------------- layer 2: HMMA half-tile, 3 CTAs/SM ----------------
// Per CTA: 128 pixels (y half) x 64 co. Chunks cc-major (k = cc*9 + tap):
// one act slab live at a time. smem: act dbuf 2 x (160 rows x 128B = 20KB),
// weight dbuf 2 x 8KB. Total 57344 B -> 3 CTAs/SM; regs capped to 85.
#define L2B_ACT(s) ((s) * 20480)
#define L2B_WT(s)  (40960 + (s) * 8192)
#define L2_SMEM 57344

__device__ __forceinline__ void l2_stage_act(uint32_t smem_base, int buf, int cc,
                                             const __nv_bfloat16* __restrict__ xg,
                                             int b, int y0, int tid) {
    for (int r = tid; r < 160; r += 256) {
        int yrel = r >> 4, xx = r & 15;
        int yg = (y0 - 1 + yrel) & 15;
        const char* src = (const char*)(xg + ((size_t)b * 256 + yg * 16 + xx) * 192 + cc * 64);
        uint32_t base = smem_base + L2B_ACT(buf);
        #pragma unroll
        for (int s = 0; s < 8; s++) {
            uint32_t off = (uint32_t)r * 128 + s * 16;
            cpasync16(base + swz(off), src + s * 16);
        }
    }
}

__device__ __forceinline__ void l2_stage_wt(uint32_t smem_base, int buf, int wc,
                                            int co0, int tid) {
    const char* wbase = (const char*)(g_w2 + ((size_t)wc * 192 + co0) * 64);
    uint32_t ra = smem_base + L2B_WT(buf);
    #pragma unroll
    for (int s2 = tid; s2 < 512; s2 += 256) {
        uint32_t off = (uint32_t)s2 * 16;
        cpasync16(ra + swz(off), wbase + off);
    }
}

__global__ void __launch_bounds__(256, 3)
l2_mma(const __nv_bfloat16* __restrict__ xg, const float* __restrict__ xf,
       const float* __restrict__ cb, const float* __restrict__ ab,
       const float* __restrict__ als, float* __restrict__ out) {
    extern __shared__ char smc[];
    __shared__ float sE[64], sAb[64];
    uint32_t smem_base = smem_u32(smc);
    const int tid = threadIdx.x;
    const int lane = tid & 31, wid = tid >> 5;
    const int b = blockIdx.x;
    const int mh = blockIdx.y;        // pixel half: y0 = mh*8
    const int co0 = blockIdx.z * 64;
    const int y0 = mh * 8;
    const int wm = wid & 1;           // 2 m-tiles of 64 px
    const int wn = wid >> 1;          // 4 n-tiles of 16 co

    if (tid < 64) {
        sE[tid] = expf(als[co0 + tid]);
        sAb[tid] = ab[co0 + tid];
    }

    // initial: act slab cc=0 -> buf0, weight chunk k=0 (wc = tap*3+cc = 0) -> buf0
    l2_stage_act(smem_base, 0, 0, xg, b, y0, tid);
    l2_stage_wt(smem_base, 0, 0, co0, tid);
    cpasync_commit();

    float d[4][2][4];
    #pragma unroll
    for (int mt = 0; mt < 4; mt++)
        #pragma unroll
        for (int nt = 0; nt < 2; nt++)
            #pragma unroll
            for (int r = 0; r < 4; r++) d[mt][nt][r] = 0.f;

    int ply[4], plx[4];
    #pragma unroll
    for (int mt = 0; mt < 4; mt++) {
        int pl = wm * 64 + mt * 16 + (lane & 15);   // 0..127
        ply[mt] = pl >> 4;                           // 0..7
        plx[mt] = pl & 15;
    }

    #pragma unroll 1
    for (int k = 0; k < 27; k++) {
        int cur = k & 1;
        int cc = k / 9, tap = k - cc * 9;
        cpasync_wait<0>();
        __syncthreads();
        if (k + 1 < 27) {
            int k1 = k + 1;
            int cc1 = k1 / 9, tap1 = k1 - cc1 * 9;
            if (cc1 != cc) l2_stage_act(smem_base, cc1 & 1, cc1, xg, b, y0, tid);
            l2_stage_wt(smem_base, 1 - cur, tap1 * 3 + cc1, co0, tid);
            cpasync_commit();
        }
        int dy = tap / 3 - 1, dx = tap % 3 - 1;
        uint32_t actb = smem_base + L2B_ACT(cc & 1);
        uint32_t wtb = smem_base + L2B_WT(cur);
        #pragma unroll
        for (int ks = 0; ks < 4; ks++) {
            uint32_t a[4][4];
            #pragma unroll
            for (int mt = 0; mt < 4; mt++) {
                int row = (ply[mt] + 1 + dy) * 16 + ((plx[mt] + dx) & 15);
                uint32_t off = (uint32_t)row * 128 + ks * 32 + (lane >> 4) * 16;
                ldsm4(a[mt], actb + swz(off));
            }
            uint32_t bf[4];
            {
                uint32_t row = wn * 16 + (lane & 7) + ((lane >> 4) << 3);
                uint32_t off = row * 128 + ks * 32 + ((lane >> 3) & 1) * 16;
                ldsm4(bf, wtb + swz(off));
            }
            #pragma unroll
            for (int mt = 0; mt < 4; mt++)
                #pragma unroll
                for (int nt = 0; nt < 2; nt++)
                    mma16816(d[mt][nt], a[mt], &bf[nt * 2]);
        }
    }

    // epilogue (R12-style access pattern)
    #pragma unroll
    for (int nt = 0; nt < 2; nt++) {
        int cr = wn * 16 + nt * 8 + (lane & 3) * 2;
        int co = co0 + cr;
        float e0 = sE[cr], e1 = sE[cr + 1];
        float ab0 = sAb[cr], ab1 = sAb[cr + 1];
        const float* cb0p = cb + (size_t)co * 256;
        const float* cb1p = cb + (size_t)(co + 1) * 256;
        float* o0p = out + ((size_t)b * 192 + co) * 256;
        float* o1p = out + ((size_t)b * 192 + co + 1) * 256;
        #pragma unroll
        for (int mt = 0; mt < 4; mt++) {
            int p = mh * 128 + wm * 64 + mt * 16 + (lane >> 2);
            const float* xf0 = xf + ((size_t)b * 256 + p) * 192;
            const float* xf8 = xf + ((size_t)b * 256 + p + 8) * 192;
            o0p[p] = (d[mt][nt][0] + xf0[co] + cb0p[p]) * e0 + ab0;
            o1p[p] = (d[mt][nt][1] + xf0[co + 1] + cb1p[p]) * e1 + ab1;
            o0p[p + 8] = (d[mt][nt][2] + xf8[co] + cb0p[p + 8]) * e0 + ab0;
            o1p[p + 8] = (d[mt][nt][3] + xf8[co + 1] + cb1p[p + 8]) * e1 + ab1;
        }
    }
}

// ---------------- launch ----------------
extern "C" void kernel_launch(void* const* d_in, const int* in_sizes, int n_in,
                              void* d_out, int out_size) {
    const float* x = (const float*)d_in[0];
    const float* k0 = (const float*)d_in[1];
    const float* cb0 = (const float*)d_in[2];
    const float* ab0 = (const float*)d_in[3];
    const float* als0 = (const float*)d_in[4];
    const float* k1 = (const float*)d_in[5];
    const float* cb1 = (const float*)d_in[6];
    const float* ab1 = (const float*)d_in[7];
    const float* als1 = (const float*)d_in[8];
    const float* k2 = (const float*)d_in[9];
    const float* cb2 = (const float*)d_in[10];
    const float* ab2 = (const float*)d_in[11];
    const float* als2 = (const float*)d_in[12];
    float* out = (float*)d_out;

    float *x1, *xf;
    __nv_bfloat16 *ag1, *xg;
    cudaGetSymbolAddress((void**)&x1, g_x1);
    cudaGetSymbolAddress((void**)&ag1, g_ag1);
    cudaGetSymbolAddress((void**)&xg, g_xg);
    cudaGetSymbolAddress((void**)&xf, g_xf32);

    const int SM0 = 12 * 324 * 4 * 4 + 12 * 9 * 12 * 8 + 12 * 2 * 4;
    cudaFuncSetAttribute((const void*)conv_layer0,
                         cudaFuncAttributeMaxDynamicSharedMemorySize, SM0);
    cudaFuncSetAttribute((const void*)l1_mma,
                         cudaFuncAttributeMaxDynamicSharedMemorySize, L1_SMEM);
    cudaFuncSetAttribute((const void*)l2_mma,
                         cudaFuncAttributeMaxDynamicSharedMemorySize, L2_SMEM);

    setup_kernel<<<2483, 256>>>(k0, k1, k2);
    conv_layer0<<<dim3(64, 16, 1), 256, SM0>>>(x, k0, cb0, ab0, als0, x1, ag1);
    l1_mma<<<dim3(256, 4), 256, L1_SMEM>>>(ag1, x1, cb1, ab1, als1, xg, xf);
    l2_mma<<<dim3(256, 2, 3), 256, L2_SMEM>>>(xg, xf, cb2, ab2, als2, out);
    fin_kernel<<<1, 256>>>(als0, als1, als2, out);
}

// round 16
// speedup vs baseline: 1.1406x; 1.0666x over previous
#include <cuda_runtime.h>
#include <cuda_bf16.h>
#include <cstdint>

// ---------------- device scratch (no allocations allowed) ----------------
__device__ __align__(16) float g_x1[256 * 12 * 64 * 64];          // L0 out squeezed-co fp32 [bq][48][1024][4]
__device__ __align__(16) __nv_bfloat16 g_ag1[256 * 1024 * 64];    // L0 out squeezed bf16 [b][p][ci(48,pad64)]
__device__ __align__(16) __nv_bfloat16 g_w1[9 * 64 * 64];         // L1 residual weights (K1 - I) bf16, padded
__device__ __align__(16) __nv_bfloat16 g_xg[256 * 256 * 192];     // L2 input bf16 [b][p][ci]
__device__ __align__(16) float g_xf32[256 * 256 * 192];           // same, fp32 (L2 center add) [b][p][ci]
__device__ __align__(16) __nv_bfloat16 g_w2[9 * 3 * 192 * 64];    // L2 residual weights (K2 - I) bf16
__device__ float g_tld[256];
__device__ float g_trT[3][9];
__device__ float g_trS[3][81];
__device__ float g_t2p[16][9];
__device__ float g_s2p[16][81];

#define X_ELEMS (256 * 192 * 16 * 16)

// ---------------- packed f32x2 helpers ----------------
__device__ __forceinline__ void ffma2(unsigned long long& d, unsigned long long a,
                                      unsigned long long b) {
    asm("fma.rn.f32x2 %0, %1, %2, %0;" : "+l"(d) : "l"(a), "l"(b));
}
__device__ __forceinline__ float2 up2(unsigned long long v) {
    float2 f;
    asm("mov.b64 {%0,%1}, %2;" : "=f"(f.x), "=f"(f.y) : "l"(v));
    return f;
}
__device__ __forceinline__ float wred(float v) {
    #pragma unroll
    for (int o = 16; o; o >>= 1) v += __shfl_xor_sync(0xffffffffu, v, o);
    return v;
}

// fast fused tanh + log1p(-tanh^2) via MUFU (ex2/rcp/lg2):
//   e = 2^(2 z log2 e);  tanh z = 1 - 2/(1+e);
//   log1p(-tanh^2 z) = ln2 * (2 + z2 - 2*lg2(1+e))
__device__ __forceinline__ void ftanh_ld(float z, float& t, float& ld) {
    float z2 = z * 2.885390081777927f;
    float e;
    asm("ex2.approx.f32 %0, %1;" : "=f"(e) : "f"(z2));
    float opE = e + 1.0f;
    float r;
    asm("rcp.approx.f32 %0, %1;" : "=f"(r) : "f"(opE));
    t = fmaf(-2.0f, r, 1.0f);
    float L;
    asm("lg2.approx.f32 %0, %1;" : "=f"(L) : "f"(opE));
    ld = 0.6931471805599453f * fmaf(-2.0f, L, 2.0f + z2);
}

// ---------------- PTX helpers ----------------
__device__ __forceinline__ uint32_t smem_u32(const void* p) {
    uint32_t a;
    asm("{ .reg .u64 t; cvta.to.shared.u64 t, %1; cvt.u32.u64 %0, t; }" : "=r"(a) : "l"(p));
    return a;
}
__device__ __forceinline__ void cpasync16(uint32_t dst, const void* src) {
    asm volatile("cp.async.cg.shared.global [%0], [%1], 16;" :: "r"(dst), "l"(src));
}
__device__ __forceinline__ void cpasync_commit() {
    asm volatile("cp.async.commit_group;" ::: "memory");
}
template <int N>
__device__ __forceinline__ void cpasync_wait() {
    asm volatile("cp.async.wait_group %0;" :: "n"(N) : "memory");
}
__device__ __forceinline__ void ldsm4(uint32_t* r, uint32_t addr) {
    asm volatile("ldmatrix.sync.aligned.m8n8.x4.shared.b16 {%0,%1,%2,%3}, [%4];"
                 : "=r"(r[0]), "=r"(r[1]), "=r"(r[2]), "=r"(r[3]) : "r"(addr));
}
__device__ __forceinline__ void mma16816(float* d, const uint32_t* a, const uint32_t* b) {
    asm volatile(
        "mma.sync.aligned.m16n8k16.row.col.f32.bf16.bf16.f32 "
        "{%0,%1,%2,%3}, {%4,%5,%6,%7}, {%8,%9}, {%0,%1,%2,%3};"
        : "+f"(d[0]), "+f"(d[1]), "+f"(d[2]), "+f"(d[3])
        : "r"(a[0]), "r"(a[1]), "r"(a[2]), "r"(a[3]), "r"(b[0]), "r"(b[1]));
}
__device__ __forceinline__ uint32_t swz(uint32_t off) { return off ^ ((off >> 3) & 0x70); }

// ---------------- trace accumulation (partial pair range) ----------------
__device__ void trace_accum(const float* __restrict__ K, int c, int lo, int hi,
                            float* __restrict__ gT, float* __restrict__ gS) {
    __shared__ float shS[81];
    __shared__ float shT[9];
    const int tid = threadIdx.x;
    if (tid < 81) shS[tid] = 0.f;
    if (tid < 9) shT[tid] = 0.f;
    __syncthreads();
    float a81[81], t9[9];
    #pragma unroll
    for (int k = 0; k < 81; k++) a81[k] = 0.f;
    #pragma unroll
    for (int k = 0; k < 9; k++) t9[k] = 0.f;
    for (int idx = lo + tid; idx < hi; idx += 256) {
        int i = idx / c, j = idx - i * c;
        const float* Ka = K + (size_t)(i * c + j) * 9;
        const float* Kb = K + (size_t)(j * c + i) * 9;
        float av[9], bv[9];
        #pragma unroll
        for (int a = 0; a < 9; a++) { av[a] = Ka[a]; bv[a] = Kb[a]; }
        #pragma unroll
        for (int a = 0; a < 9; a++)
            #pragma unroll
            for (int b = 0; b < 9; b++) a81[a * 9 + b] += av[a] * bv[b];
        if (i == j) {
            #pragma unroll
            for (int a = 0; a < 9; a++) t9[a] += av[a];
        }
    }
    #pragma unroll
    for (int k = 0; k < 81; k++) atomicAdd(&shS[k], a81[k]);
    #pragma unroll
    for (int k = 0; k < 9; k++) atomicAdd(&shT[k], t9[k]);
    __syncthreads();
    if (tid < 81) gS[tid] = shS[tid];
    if (tid < 9) gT[tid] = shT[tid];
}

// ---------------- fused setup ----------------
__global__ void setup_kernel(const float* __restrict__ K0, const float* __restrict__ K1,
                             const float* __restrict__ K2) {
    int bid = blockIdx.x, tid = threadIdx.x;
    if (bid == 0) {
        g_tld[tid] = 0.f;
    } else if (bid <= 1024) {
        int idx = (bid - 1) * 256 + tid;
        uint4 z = make_uint4(0, 0, 0, 0);
        *(uint4*)(g_ag1 + (size_t)idx * 64 + 48) = z;
        *(uint4*)(g_ag1 + (size_t)idx * 64 + 56) = z;
    } else if (bid <= 1168) {
        int idx = (bid - 1025) * 256 + tid;
        int cil = idx & 63;
        int r = idx >> 6;
        int co = r % 64;
        int tap = r / 64;
        float w = 0.f;
        if (co < 48 && cil < 48) {
            w = K1[((size_t)co * 48 + cil) * 9 + tap];
            if (tap == 4 && cil == co) w -= 1.0f;
        }
        g_w1[idx] = __float2bfloat16(w);
    } else if (bid <= 2464) {
        int idx = (bid - 1169) * 256 + tid;
        int cil = idx & 63;
        int r = idx >> 6;
        int co = r % 192;
        int q = r / 192;
        int cc = q % 3;
        int tap = q / 3;
        int ci = cc * 64 + cil;
        float w = K2[((size_t)co * 192 + ci) * 9 + tap];
        if (tap == 4 && ci == co) w -= 1.0f;
        g_w2[idx] = __float2bfloat16(w);
    } else if (bid == 2465) {
        trace_accum(K0, 12, 0, 144, g_trT[0], g_trS[0]);
    } else if (bid == 2466) {
        trace_accum(K1, 48, 0, 2304, g_trT[1], g_trS[1]);
    } else {
        int blk = bid - 2467;
        trace_accum(K2, 192, blk * 2304, (blk + 1) * 2304, g_t2p[blk], g_s2p[blk]);
    }
}

// ---------------- finalize ----------------
__device__ __forceinline__ float2 cmul(float2 a, float2 b) {
    return make_float2(a.x * b.x - a.y * b.y, a.x * b.y + a.y * b.x);
}

__global__ void fin_kernel(const float* __restrict__ a0, const float* __restrict__ a1,
                           const float* __restrict__ a2, float* __restrict__ out) {
    __shared__ float shT[9], shS[81], red[8];
    __shared__ float stot;
    const int tid = threadIdx.x;
    float part = 0.f;
    #pragma unroll 1
    for (int L = 0; L < 3; L++) {
        const float* als = (L == 0) ? a0 : ((L == 1) ? a1 : a2);
        const int c = (L == 0) ? 12 : ((L == 1) ? 48 : 192);
        const int n = (L == 0) ? 64 : ((L == 1) ? 32 : 16);
        __syncthreads();
        if (tid < 9) {
            float s;
            if (L < 2) s = g_trT[L][tid];
            else {
                s = 0.f;
                #pragma unroll
                for (int p = 0; p < 16; p++) s += g_t2p[p][tid];
            }
            shT[tid] = s;
        }
        if (tid < 81) {
            float s;
            if (L < 2) s = g_trS[L][tid];
            else {
                s = 0.f;
                #pragma unroll
                for (int p = 0; p < 16; p++) s += g_s2p[p][tid];
            }
            shS[tid] = s;
        }
        __syncthreads();
        for (int f = tid; f < n * n; f += 256) {
            int u = f / n, v = f - u * n;
            float su, cu, sv, cv;
            sincosf(-6.283185307179586f * (float)u / (float)n, &su, &cu);
            sincosf(-6.283185307179586f * (float)v / (float)n, &sv, &cv);
            float2 eu = make_float2(cu, su), ev = make_float2(cv, sv);
            float2 pU[3] = {make_float2(1.f, 0.f), eu, cmul(eu, eu)};
            float2 pV[3] = {make_float2(1.f, 0.f), ev, cmul(ev, ev)};
            float2 ph[9];
            #pragma unroll
            for (int dy = 0; dy < 3; dy++)
                #pragma unroll
                for (int dx = 0; dx < 3; dx++) ph[dy * 3 + dx] = cmul(pU[dy], pV[dx]);
            float2 T = make_float2(0.f, 0.f), T2 = make_float2(0.f, 0.f);
            #pragma unroll
            for (int a = 0; a < 9; a++) {
                T.x += shT[a] * ph[a].x;
                T.y += shT[a] * ph[a].y;
            }
            #pragma unroll
            for (int a = 0; a < 9; a++) {
                float2 inner = make_float2(0.f, 0.f);
                #pragma unroll
                for (int b = 0; b < 9; b++) {
                    float s = shS[a * 9 + b];
                    inner.x += s * ph[b].x;
                    inner.y += s * ph[b].y;
                }
                float2 pi = cmul(ph[a], inner);
                T2.x += pi.x;
                T2.y += pi.y;
            }
            float2 e1 = cmul(pU[1], pV[1]);
            e1.y = -e1.y;
            float2 e2 = cmul(e1, e1);
            float A = e1.x * T.x - e1.y * T.y;
            float B = e2.x * T2.x - e2.y * T2.y;
            part += 2.f * A - 1.5f * (float)c - 0.5f * B;
        }
        float as = 0.f;
        for (int k = tid; k < c; k += 256) as += als[k];
        part += (float)(n * n) * as;
    }
    float w = wred(part);
    if ((tid & 31) == 0) red[tid >> 5] = w;
    __syncthreads();
    if (tid == 0) {
        float s = 0.f;
        #pragma unroll
        for (int q = 0; q < 8; q++) s += red[q];
        stot = s;
    }
    __syncthreads();
    out[X_ELEMS + tid] = stot + g_tld[tid];
}

// ---------------- layer 0: fused FFMA conv (fast tanh epilogue) --------------
__global__ void __launch_bounds__(256, 2)
conv_layer0(const float* __restrict__ X, const float* __restrict__ Kw,
            const float* __restrict__ cb, const float* __restrict__ ab,
            const float* __restrict__ als, float* __restrict__ Y,
            __nv_bfloat16* __restrict__ YB) {
    constexpr int CPREV = 3, N = 64, CI_CHUNK = 12, OUT_BLK = 12;
    constexpr int CIN = 12, H = 128;
    constexpr int S_FLOATS = CI_CHUNK * 324 * 4;
    extern __shared__ float smem[];
    float* S = smem;
    float2* KS = (float2*)(smem + S_FLOATS);
    float* sE = (float*)(KS + CI_CHUNK * 9 * OUT_BLK);
    float* sAb = sE + OUT_BLK;

    const int tid = threadIdx.x;
    const int bq = blockIdx.x;
    const int b0 = bq * 4;
    constexpr int TILES_X = N / 16;
    const int ty = (blockIdx.y / TILES_X) * 16;
    const int tx = (blockIdx.y % TILES_X) * 16;
    const int py = tid >> 4, px = tid & 15;

    if (tid < OUT_BLK) {
        sE[tid] = expf(als[tid]);
        sAb[tid] = ab[tid];
    }

    unsigned long long accA[OUT_BLK], accB[OUT_BLK];
    #pragma unroll
    for (int o = 0; o < OUT_BLK; o++) { accA[o] = 0ull; accB[o] = 0ull; }

    {
        __syncthreads();
        for (int idx = tid; idx < CI_CHUNK * 324; idx += 256) {
            int ci = idx / 324;
            int rem = idx - ci * 324;
            int yy = rem / 18, xx = rem - yy * 18;
            int g = ci / CPREV;
            int cc = ci - g * CPREV;
            int gy = ty + yy - 1;
            if (gy < 0) gy += N;
            if (gy >= N) gy -= N;
            int gx = tx + xx - 1;
            if (gx < 0) gx += N;
            if (gx >= N) gx -= N;
            int sy = 2 * gy + (g & 1);
            int sx = 2 * gx + ((g ^ (g >> 1)) & 1);
            size_t base = ((size_t)cc * H + sy) * H + sx;
            size_t bstr = (size_t)CPREV * H * H;
            float4 val;
            val.x = X[base + (size_t)(b0 + 0) * bstr];
            val.y = X[base + (size_t)(b0 + 1) * bstr];
            val.z = X[base + (size_t)(b0 + 2) * bstr];
            val.w = X[base + (size_t)(b0 + 3) * bstr];
            *(float4*)(S + idx * 4) = val;
        }
        for (int idx = tid; idx < CI_CHUNK * 9 * OUT_BLK; idx += 256) {
            int ci = idx / (9 * OUT_BLK);
            int rem = idx - ci * 9 * OUT_BLK;
            int tap = rem / OUT_BLK;
            int o = rem - tap * OUT_BLK;
            float k = Kw[((size_t)o * CIN + ci) * 9 + tap];
            KS[idx] = make_float2(k, k);
        }
        __syncthreads();

        #pragma unroll 1
        for (int ci = 0; ci < CI_CHUNK; ci++) {
            const float* Sci = S + ci * 1296;
            const float2* Kci = KS + ci * 9 * OUT_BLK;
            #pragma unroll
            for (int tap = 0; tap < 9; tap++) {
                int dy = tap / 3, dx = tap - dy * 3;
                ulonglong2 v =
                    *(const ulonglong2*)(Sci + ((py + dy) * 18 + (px + dx)) * 4);
                #pragma unroll
                for (int o = 0; o < OUT_BLK; o += 2) {
                    ulonglong2 kk = *(const ulonglong2*)(Kci + tap * OUT_BLK + o);
                    ffma2(accA[o], kk.x, v.x);
                    ffma2(accB[o], kk.x, v.y);
                    ffma2(accA[o + 1], kk.y, v.x);
                    ffma2(accB[o + 1], kk.y, v.y);
                }
            }
        }
    }

    const int i = ty + py, j = tx + px;
    const int y = i >> 1, x = j >> 1;
    const int hs = i & 1, ws = j & 1;
    const int g = (hs == ws) ? hs : (2 + hs);
    const int p = y * 32 + x;
    float ld[4] = {0.f, 0.f, 0.f, 0.f};
    uint32_t pk[6][4];

    #pragma unroll
    for (int o = 0; o < OUT_BLK; o += 2) {
        float e0 = sE[o], a0v = sAb[o];
        float e1 = sE[o + 1], a1v = sAb[o + 1];
        float c0v = cb[((size_t)o * N + i) * N + j];
        float c1v = cb[((size_t)(o + 1) * N + i) * N + j];
        float2 pA0 = up2(accA[o]), pB0 = up2(accB[o]);
        float2 pA1 = up2(accA[o + 1]), pB1 = up2(accB[o + 1]);
        float z0[4] = {pA0.x, pA0.y, pB0.x, pB0.y};
        float z1[4] = {pA1.x, pA1.y, pB1.x, pB1.y};
        float t0[4], t1[4];
        #pragma unroll
        for (int nb = 0; nb < 4; nb++) {
            float l0, l1v;
            ftanh_ld((z0[nb] + c0v) * e0 + a0v, t0[nb], l0);
            ftanh_ld((z1[nb] + c1v) * e1 + a1v, t1[nb], l1v);
            ld[nb] += l0 + l1v;
            __nv_bfloat162 p2;
            p2.x = __float2bfloat16(t0[nb]);
            p2.y = __float2bfloat16(t1[nb]);
            pk[o >> 1][nb] = *(uint32_t*)&p2;
        }
        *(float4*)(Y + (((size_t)bq * 48 + g * 12 + o) * 1024 + p) * 4) =
            make_float4(t0[0], t0[1], t0[2], t0[3]);
        *(float4*)(Y + (((size_t)bq * 48 + g * 12 + o + 1) * 1024 + p) * 4) =
            make_float4(t1[0], t1[1], t1[2], t1[3]);
    }

    {
        #pragma unroll
        for (int nb = 0; nb < 4; nb++) {
            size_t base = ((size_t)(b0 + nb) * 1024 + p) * 64 + g * 12;
            *(uint2*)(YB + base) = make_uint2(pk[0][nb], pk[1][nb]);
            *(uint2*)(YB + base + 4) = make_uint2(pk[2][nb], pk[3][nb]);
            *(uint2*)(YB + base + 8) = make_uint2(pk[4][nb], pk[5][nb]);
        }
    }

    #pragma unroll
    for (int nb = 0; nb < 4; nb++) ld[nb] = wred(ld[nb]);
    __syncthreads();
    float* red = S;
    if ((tid & 31) == 0) {
        int w = tid >> 5;
        red[w * 4 + 0] = ld[0];
        red[w * 4 + 1] = ld[1];
        red[w * 4 + 2] = ld[2];
        red[w * 4 + 3] = ld[3];
    }
    __syncthreads();
    if (tid < 4) {
        float s = 0.f;
        #pragma unroll
        for (int w = 0; w < 8; w++) s += red[w * 4 + tid];
        atomicAdd(&g_tld[b0 + tid], s);
    }
}

// ---------------- layer 1: HMMA, single-stage smem (fast tanh epilogue) ------
#define L1_WT_BASE 40960
#define L1_SMEM 114688

__global__ void __launch_bounds__(256, 2)
l1_mma(const __nv_bfloat16* __restrict__ ag, const float* __restrict__ x1p,
       const float* __restrict__ cb, const float* __restrict__ ab,
       const float* __restrict__ als,
       __nv_bfloat16* __restrict__ xg, float* __restrict__ xf) {
    extern __shared__ char smc[];
    __shared__ float sE[48], sAb[48], red[8];
    uint32_t smem_base = smem_u32(smc);
    const int tid = threadIdx.x;
    const int lane = tid & 31, wid = tid >> 5;
    const int b = blockIdx.x;
    const int mt0 = blockIdx.y * 256;
    const int ytile0 = mt0 >> 5;
    const int m0 = (wid & 3) * 64;
    const int n0 = (wid >> 2) * 32;
    const int bq = b >> 2, nb = b & 3;

    if (tid < 48) {
        sE[tid] = expf(als[tid]);
        sAb[tid] = ab[tid];
    }

    for (int r = tid; r < 320; r += 256) {
        int yrel = r >> 5, x = r & 31;
        int yg = (ytile0 - 1 + yrel) & 31;
        const char* src = (const char*)(ag + ((size_t)b * 1024 + yg * 32 + x) * 64);
        #pragma unroll
        for (int s = 0; s < 8; s++) {
            uint32_t off = (uint32_t)r * 128 + s * 16;
            cpasync16(smem_base + swz(off), src + s * 16);
        }
    }
    for (int r = tid; r < 576; r += 256) {
        const char* src = (const char*)(g_w1 + (size_t)r * 64);
        #pragma unroll
        for (int s = 0; s < 8; s++) {
            uint32_t off = (uint32_t)r * 128 + s * 16;
            cpasync16(smem_base + L1_WT_BASE + swz(off), src + s * 16);
        }
    }
    cpasync_commit();

    float d[4][4][4];
    #pragma unroll
    for (int mt = 0; mt < 4; mt++)
        #pragma unroll
        for (int nt = 0; nt < 4; nt++)
            #pragma unroll
            for (int r = 0; r < 4; r++) d[mt][nt][r] = 0.f;

    int ply[4], plx[4];
    #pragma unroll
    for (int mt = 0; mt < 4; mt++) {
        int pl = m0 + mt * 16 + (lane & 15);
        ply[mt] = pl >> 5;
        plx[mt] = pl & 31;
    }

    cpasync_wait<0>();
    __syncthreads();

    #pragma unroll 1
    for (int c = 0; c < 9; c++) {
        int dy = c / 3 - 1, dx = c % 3 - 1;
        #pragma unroll
        for (int ks = 0; ks < 4; ks++) {
            uint32_t a[4][4];
            #pragma unroll
            for (int mt = 0; mt < 4; mt++) {
                int row = (ply[mt] + 1 + dy) * 32 + ((plx[mt] + dx) & 31);
                uint32_t off = (uint32_t)row * 128 + ks * 32 + (lane >> 4) * 16;
                ldsm4(a[mt], smem_base + swz(off));
            }
            uint32_t bf[2][4];
            #pragma unroll
            for (int nh = 0; nh < 2; nh++) {
                uint32_t row = c * 64 + n0 + nh * 16 + (lane & 7) + ((lane >> 4) << 3);
                uint32_t off = row * 128 + ks * 32 + ((lane >> 3) & 1) * 16;
                ldsm4(bf[nh], smem_base + L1_WT_BASE + swz(off));
            }
            #pragma unroll
            for (int mt = 0; mt < 4; mt++)
                #pragma unroll
                for (int nt = 0; nt < 4; nt++)
                    mma16816(d[mt][nt], a[mt], &bf[nt >> 1][(nt & 1) * 2]);
        }
    }

    float ldsum = 0.f;
    #pragma unroll
    for (int nt = 0; nt < 4; nt++) {
        int co = n0 + nt * 8 + (lane & 3) * 2;
        if (co < 48) {
            float e0 = sE[co], e1 = sE[co + 1];
            float ab0 = sAb[co], ab1 = sAb[co + 1];
            const float* xc0p = x1p + ((size_t)bq * 48 + co) * 4096 + nb;
            const float* xc1p = x1p + ((size_t)bq * 48 + co + 1) * 4096 + nb;
            #pragma unroll
            for (int mt = 0; mt < 4; mt++) {
                #pragma unroll
                for (int half = 0; half < 2; half++) {
                    int p = mt0 + m0 + mt * 16 + (lane >> 2) + half * 8;
                    float xc0 = xc0p[p * 4];
                    float xc1 = xc1p[p * 4];
                    float z0 = d[mt][nt][half * 2] + xc0 + cb[(size_t)co * 1024 + p];
                    float z1 = d[mt][nt][half * 2 + 1] + xc1 + cb[(size_t)(co + 1) * 1024 + p];
                    float t0, t1, l0, l1v;
                    ftanh_ld(z0 * e0 + ab0, t0, l0);
                    ftanh_ld(z1 * e1 + ab1, t1, l1v);
                    ldsum += l0 + l1v;
                    int i = p >> 5, j = p & 31;
                    int y = i >> 1, x = j >> 1;
                    int hs = i & 1, ws = j & 1;
                    int g = (hs == ws) ? hs : (2 + hs);
                    size_t xi = ((size_t)b * 256 + y * 16 + x) * 192 + g * 48 + co;
                    __nv_bfloat162 pk2;
                    pk2.x = __float2bfloat16(t0);
                    pk2.y = __float2bfloat16(t1);
                    *(__nv_bfloat162*)(xg + xi) = pk2;
                    *(float2*)(xf + xi) = make_float2(t0, t1);
                }
            }
        }
    }
    ldsum = wred(ldsum);
    if (lane == 0) red[wid] = ldsum;
    __syncthreads();
    if (tid == 0) {
        float s = 0.f;
        #pragma unroll
        for (int w = 0; w < 8; w++) s += red[w];
        atomicAdd(&g_tld[b], s);
    }
}

// ---------------- layer 2: HMMA half-tile, 32px x 32co warp tiles ------------
// Per CTA: 128 pixels (y half) x 64 co. Chunks cc-major (k = cc*9 + tap).
// Warp tile 32 px x 32 co: per ks 2 a-ldsm + 2 b-ldsm -> 8 MMAs (ldsm/MMA 0.5).
#define L2B_ACT(s) ((s) * 20480)
#define L2B_WT(s)  (40960 + (s) * 8192)
#define L2_SMEM 57344

__device__ __forceinline__ void l2_stage_act(uint32_t smem_base, int buf, int cc,
                                             const __nv_bfloat16* __restrict__ xg,
                                             int b, int y0, int tid) {
    for (int r = tid; r < 160; r += 256) {
        int yrel = r >> 4, xx = r & 15;
        int yg = (y0 - 1 + yrel) & 15;
        const char* src = (const char*)(xg + ((size_t)b * 256 + yg * 16 + xx) * 192 + cc * 64);
        uint32_t base = smem_base + L2B_ACT(buf);
        #pragma unroll
        for (int s = 0; s < 8; s++) {
            uint32_t off = (uint32_t)r * 128 + s * 16;
            cpasync16(base + swz(off), src + s * 16);
        }
    }
}

__device__ __forceinline__ void l2_stage_wt(uint32_t smem_base, int buf, int wc,
                                            int co0, int tid) {
    const char* wbase = (const char*)(g_w2 + ((size_t)wc * 192 + co0) * 64);
    uint32_t ra = smem_base + L2B_WT(buf);
    #pragma unroll
    for (int s2 = tid; s2 < 512; s2 += 256) {
        uint32_t off = (uint32_t)s2 * 16;
        cpasync16(ra + swz(off), wbase + off);
    }
}

__global__ void __launch_bounds__(256, 3)
l2_mma(const __nv_bfloat16* __restrict__ xg, const float* __restrict__ xf,
       const float* __restrict__ cb, const float* __restrict__ ab,
       const float* __restrict__ als, float* __restrict__ out) {
    extern __shared__ char smc[];
    __shared__ float sE[64], sAb[64];
    uint32_t smem_base = smem_u32(smc);
    const int tid = threadIdx.x;
    const int lane = tid & 31, wid = tid >> 5;
    const int b = blockIdx.x;
    const int mh = blockIdx.y;        // pixel half: y0 = mh*8
    const int co0 = blockIdx.z * 64;
    const int y0 = mh * 8;
    const int wm = wid & 3;           // 4 m-tiles of 32 px
    const int wn = wid >> 2;          // 2 n-tiles of 32 co

    if (tid < 64) {
        sE[tid] = expf(als[co0 + tid]);
        sAb[tid] = ab[co0 + tid];
    }

    l2_stage_act(smem_base, 0, 0, xg, b, y0, tid);
    l2_stage_wt(smem_base, 0, 0, co0, tid);
    cpasync_commit();

    float d[2][4][4];
    #pragma unroll
    for (int mt = 0; mt < 2; mt++)
        #pragma unroll
        for (int nt = 0; nt < 4; nt++)
            #pragma unroll
            for (int r = 0; r < 4; r++) d[mt][nt][r] = 0.f;

    int ply[2], plx[2];
    #pragma unroll
    for (int mt = 0; mt < 2; mt++) {
        int pl = wm * 32 + mt * 16 + (lane & 15);   // 0..127
        ply[mt] = pl >> 4;                           // 0..7
        plx[mt] = pl & 15;
    }

    #pragma unroll 1
    for (int k = 0; k < 27; k++) {
        int cur = k & 1;
        int cc = k / 9, tap = k - cc * 9;
        cpasync_wait<0>();
        __syncthreads();
        if (k + 1 < 27) {
            int k1 = k + 1;
            int cc1 = k1 / 9, tap1 = k1 - cc1 * 9;
            if (cc1 != cc) l2_stage_act(smem_base, cc1 & 1, cc1, xg, b, y0, tid);
            l2_stage_wt(smem_base, 1 - cur, tap1 * 3 + cc1, co0, tid);
            cpasync_commit();
        }
        int dy = tap / 3 - 1, dx = tap % 3 - 1;
        uint32_t actb = smem_base + L2B_ACT(cc & 1);
        uint32_t wtb = smem_base + L2B_WT(cur);
        #pragma unroll
        for (int ks = 0; ks < 4; ks++) {
            uint32_t a[2][4];
            #pragma unroll
            for (int mt = 0; mt < 2; mt++) {
                int row = (ply[mt] + 1 + dy) * 16 + ((plx[mt] + dx) & 15);
                uint32_t off = (uint32_t)row * 128 + ks * 32 + (lane >> 4) * 16;
                ldsm4(a[mt], actb + swz(off));
            }
            uint32_t bf[2][4];
            #pragma unroll
            for (int nh = 0; nh < 2; nh++) {
                uint32_t row = wn * 32 + nh * 16 + (lane & 7) + ((lane >> 4) << 3);
                uint32_t off = row * 128 + ks * 32 + ((lane >> 3) & 1) * 16;
                ldsm4(bf[nh], wtb + swz(off));
            }
            #pragma unroll
            for (int mt = 0; mt < 2; mt++)
                #pragma unroll
                for (int nt = 0; nt < 4; nt++)
                    mma16816(d[mt][nt], a[mt], &bf[nt >> 1][(nt & 1) * 2]);
        }
    }

    // epilogue
    #pragma unroll
    for (int nt = 0; nt < 4; nt++) {
        int cr = wn * 32 + (nt >> 1) * 16 + (nt & 1) * 8 + (lane & 3) * 2;
        int co = co0 + cr;
        float e0 = sE[cr], e1 = sE[cr + 1];
        float ab0 = sAb[cr], ab1 = sAb[cr + 1];
        const float* cb0p = cb + (size_t)co * 256;
        const float* cb1p = cb + (size_t)(co + 1) * 256;
        float* o0p = out + ((size_t)b * 192 + co) * 256;
        float* o1p = out + ((size_t)b * 192 + co + 1) * 256;
        #pragma unroll
        for (int mt = 0; mt < 2; mt++) {
            int p = mh * 128 + wm * 32 + mt * 16 + (lane >> 2);
            const float* xf0 = xf + ((size_t)b * 256 + p) * 192;
            const float* xf8 = xf + ((size_t)b * 256 + p + 8) * 192;
            o0p[p] = (d[mt][nt][0] + xf0[co] + cb0p[p]) * e0 + ab0;
            o1p[p] = (d[mt][nt][1] + xf0[co + 1] + cb1p[p]) * e1 + ab1;
            o0p[p + 8] = (d[mt][nt][2] + xf8[co] + cb0p[p + 8]) * e0 + ab0;
            o1p[p + 8] = (d[mt][nt][3] + xf8[co + 1] + cb1p[p + 8]) * e1 + ab1;
        }
    }
}

// ---------------- launch ----------------
extern "C" void kernel_launch(void* const* d_in, const int* in_sizes, int n_in,
                              void* d_out, int out_size) {
    const float* x = (const float*)d_in[0];
    const float* k0 = (const float*)d_in[1];
    const float* cb0 = (const float*)d_in[2];
    const float* ab0 = (const float*)d_in[3];
    const float* als0 = (const float*)d_in[4];
    const float* k1 = (const float*)d_in[5];
    const float* cb1 = (const float*)d_in[6];
    const float* ab1 = (const float*)d_in[7];
    const float* als1 = (const float*)d_in[8];
    const float* k2 = (const float*)d_in[9];
    const float* cb2 = (const float*)d_in[10];
    const float* ab2 = (const float*)d_in[11];
    const float* als2 = (const float*)d_in[12];
    float* out = (float*)d_out;

    float *x1, *xf;
    __nv_bfloat16 *ag1, *xg;
    cudaGetSymbolAddress((void**)&x1, g_x1);
    cudaGetSymbolAddress((void**)&ag1, g_ag1);
    cudaGetSymbolAddress((void**)&xg, g_xg);
    cudaGetSymbolAddress((void**)&xf, g_xf32);

    const int SM0 = 12 * 324 * 4 * 4 + 12 * 9 * 12 * 8 + 12 * 2 * 4;
    cudaFuncSetAttribute((const void*)conv_layer0,
                         cudaFuncAttributeMaxDynamicSharedMemorySize, SM0);
    cudaFuncSetAttribute((const void*)l1_mma,
                         cudaFuncAttributeMaxDynamicSharedMemorySize, L1_SMEM);
    cudaFuncSetAttribute((const void*)l2_mma,
                         cudaFuncAttributeMaxDynamicSharedMemorySize, L2_SMEM);

    setup_kernel<<<2483, 256>>>(k0, k1, k2);
    conv_layer0<<<dim3(64, 16, 1), 256, SM0>>>(x, k0, cb0, ab0, als0, x1, ag1);
    l1_mma<<<dim3(256, 4), 256, L1_SMEM>>>(ag1, x1, cb1, ab1, als1, xg, xf);
    l2_mma<<<dim3(256, 2, 3), 256, L2_SMEM>>>(xg, xf, cb2, ab2, als2, out);
    fin_kernel<<<1, 256>>>(als0, als1, als2, out);
}

// round 17
// speedup vs baseline: 1.1785x; 1.0333x over previous
#include <cuda_runtime.h>
#include <cuda_bf16.h>
#include <cstdint>

// ---------------- device scratch (no allocations allowed) ----------------
__device__ __align__(16) float g_x1[256 * 12 * 64 * 64];          // L0 out squeezed-co fp32 [bq][48][1024][4]
__device__ __align__(16) __nv_bfloat16 g_ag1[256 * 1024 * 64];    // L0 out squeezed bf16 [b][p][ci(48,pad64)]
__device__ __align__(16) __nv_bfloat16 g_w1[9 * 64 * 64];         // L1 residual weights (K1 - I) bf16, padded
__device__ __align__(16) __nv_bfloat16 g_xg[256 * 256 * 192];     // L2 input bf16 [b][p][ci]
__device__ __align__(16) float g_xf32[256 * 256 * 192];           // same, fp32 (L2 center add) [b][p][ci]
__device__ __align__(16) __nv_bfloat16 g_w2[9 * 3 * 192 * 64];    // L2 residual weights (K2 - I) bf16
__device__ float g_tld[256];
__device__ float g_trT[3][9];
__device__ float g_trS[3][81];
__device__ float g_t2p[16][9];
__device__ float g_s2p[16][81];

#define X_ELEMS (256 * 192 * 16 * 16)

// ---------------- packed f32x2 helpers ----------------
__device__ __forceinline__ void ffma2(unsigned long long& d, unsigned long long a,
                                      unsigned long long b) {
    asm("fma.rn.f32x2 %0, %1, %2, %0;" : "+l"(d) : "l"(a), "l"(b));
}
__device__ __forceinline__ float2 up2(unsigned long long v) {
    float2 f;
    asm("mov.b64 {%0,%1}, %2;" : "=f"(f.x), "=f"(f.y) : "l"(v));
    return f;
}
__device__ __forceinline__ float wred(float v) {
    #pragma unroll
    for (int o = 16; o; o >>= 1) v += __shfl_xor_sync(0xffffffffu, v, o);
    return v;
}

// fast fused tanh + log1p(-tanh^2) via MUFU (ex2/rcp/lg2)
__device__ __forceinline__ void ftanh_ld(float z, float& t, float& ld) {
    float z2 = z * 2.885390081777927f;
    float e;
    asm("ex2.approx.f32 %0, %1;" : "=f"(e) : "f"(z2));
    float opE = e + 1.0f;
    float r;
    asm("rcp.approx.f32 %0, %1;" : "=f"(r) : "f"(opE));
    t = fmaf(-2.0f, r, 1.0f);
    float L;
    asm("lg2.approx.f32 %0, %1;" : "=f"(L) : "f"(opE));
    ld = 0.6931471805599453f * fmaf(-2.0f, L, 2.0f + z2);
}

// ---------------- PTX helpers ----------------
__device__ __forceinline__ uint32_t smem_u32(const void* p) {
    uint32_t a;
    asm("{ .reg .u64 t; cvta.to.shared.u64 t, %1; cvt.u32.u64 %0, t; }" : "=r"(a) : "l"(p));
    return a;
}
__device__ __forceinline__ void cpasync16(uint32_t dst, const void* src) {
    asm volatile("cp.async.cg.shared.global [%0], [%1], 16;" :: "r"(dst), "l"(src));
}
__device__ __forceinline__ void cpasync_commit() {
    asm volatile("cp.async.commit_group;" ::: "memory");
}
template <int N>
__device__ __forceinline__ void cpasync_wait() {
    asm volatile("cp.async.wait_group %0;" :: "n"(N) : "memory");
}
__device__ __forceinline__ void ldsm4(uint32_t* r, uint32_t addr) {
    asm volatile("ldmatrix.sync.aligned.m8n8.x4.shared.b16 {%0,%1,%2,%3}, [%4];"
                 : "=r"(r[0]), "=r"(r[1]), "=r"(r[2]), "=r"(r[3]) : "r"(addr));
}
__device__ __forceinline__ void mma16816(float* d, const uint32_t* a, const uint32_t* b) {
    asm volatile(
        "mma.sync.aligned.m16n8k16.row.col.f32.bf16.bf16.f32 "
        "{%0,%1,%2,%3}, {%4,%5,%6,%7}, {%8,%9}, {%0,%1,%2,%3};"
        : "+f"(d[0]), "+f"(d[1]), "+f"(d[2]), "+f"(d[3])
        : "r"(a[0]), "r"(a[1]), "r"(a[2]), "r"(a[3]), "r"(b[0]), "r"(b[1]));
}
__device__ __forceinline__ uint32_t swz(uint32_t off) { return off ^ ((off >> 3) & 0x70); }

// ---------------- trace accumulation (partial pair range) ----------------
__device__ void trace_accum(const float* __restrict__ K, int c, int lo, int hi,
                            float* __restrict__ gT, float* __restrict__ gS) {
    __shared__ float shS[81];
    __shared__ float shT[9];
    const int tid = threadIdx.x;
    if (tid < 81) shS[tid] = 0.f;
    if (tid < 9) shT[tid] = 0.f;
    __syncthreads();
    float a81[81], t9[9];
    #pragma unroll
    for (int k = 0; k < 81; k++) a81[k] = 0.f;
    #pragma unroll
    for (int k = 0; k < 9; k++) t9[k] = 0.f;
    for (int idx = lo + tid; idx < hi; idx += 256) {
        int i = idx / c, j = idx - i * c;
        const float* Ka = K + (size_t)(i * c + j) * 9;
        const float* Kb = K + (size_t)(j * c + i) * 9;
        float av[9], bv[9];
        #pragma unroll
        for (int a = 0; a < 9; a++) { av[a] = Ka[a]; bv[a] = Kb[a]; }
        #pragma unroll
        for (int a = 0; a < 9; a++)
            #pragma unroll
            for (int b = 0; b < 9; b++) a81[a * 9 + b] += av[a] * bv[b];
        if (i == j) {
            #pragma unroll
            for (int a = 0; a < 9; a++) t9[a] += av[a];
        }
    }
    #pragma unroll
    for (int k = 0; k < 81; k++) atomicAdd(&shS[k], a81[k]);
    #pragma unroll
    for (int k = 0; k < 9; k++) atomicAdd(&shT[k], t9[k]);
    __syncthreads();
    if (tid < 81) gS[tid] = shS[tid];
    if (tid < 9) gT[tid] = shT[tid];
}

// ---------------- fused setup ----------------
__global__ void setup_kernel(const float* __restrict__ K0, const float* __restrict__ K1,
                             const float* __restrict__ K2) {
    int bid = blockIdx.x, tid = threadIdx.x;
    if (bid == 0) {
        g_tld[tid] = 0.f;
    } else if (bid <= 1024) {
        int idx = (bid - 1) * 256 + tid;
        uint4 z = make_uint4(0, 0, 0, 0);
        *(uint4*)(g_ag1 + (size_t)idx * 64 + 48) = z;
        *(uint4*)(g_ag1 + (size_t)idx * 64 + 56) = z;
    } else if (bid <= 1168) {
        int idx = (bid - 1025) * 256 + tid;
        int cil = idx & 63;
        int r = idx >> 6;
        int co = r % 64;
        int tap = r / 64;
        float w = 0.f;
        if (co < 48 && cil < 48) {
            w = K1[((size_t)co * 48 + cil) * 9 + tap];
            if (tap == 4 && cil == co) w -= 1.0f;
        }
        g_w1[idx] = __float2bfloat16(w);
    } else if (bid <= 2464) {
        int idx = (bid - 1169) * 256 + tid;
        int cil = idx & 63;
        int r = idx >> 6;
        int co = r % 192;
        int q = r / 192;
        int cc = q % 3;
        int tap = q / 3;
        int ci = cc * 64 + cil;
        float w = K2[((size_t)co * 192 + ci) * 9 + tap];
        if (tap == 4 && ci == co) w -= 1.0f;
        g_w2[idx] = __float2bfloat16(w);
    } else if (bid == 2465) {
        trace_accum(K0, 12, 0, 144, g_trT[0], g_trS[0]);
    } else if (bid == 2466) {
        trace_accum(K1, 48, 0, 2304, g_trT[1], g_trS[1]);
    } else {
        int blk = bid - 2467;
        trace_accum(K2, 192, blk * 2304, (blk + 1) * 2304, g_t2p[blk], g_s2p[blk]);
    }
}

// ---------------- finalize ----------------
__device__ __forceinline__ float2 cmul(float2 a, float2 b) {
    return make_float2(a.x * b.x - a.y * b.y, a.x * b.y + a.y * b.x);
}

__global__ void fin_kernel(const float* __restrict__ a0, const float* __restrict__ a1,
                           const float* __restrict__ a2, float* __restrict__ out) {
    __shared__ float shT[9], shS[81], red[8];
    __shared__ float stot;
    const int tid = threadIdx.x;
    float part = 0.f;
    #pragma unroll 1
    for (int L = 0; L < 3; L++) {
        const float* als = (L == 0) ? a0 : ((L == 1) ? a1 : a2);
        const int c = (L == 0) ? 12 : ((L == 1) ? 48 : 192);
        const int n = (L == 0) ? 64 : ((L == 1) ? 32 : 16);
        __syncthreads();
        if (tid < 9) {
            float s;
            if (L < 2) s = g_trT[L][tid];
            else {
                s = 0.f;
                #pragma unroll
                for (int p = 0; p < 16; p++) s += g_t2p[p][tid];
            }
            shT[tid] = s;
        }
        if (tid < 81) {
            float s;
            if (L < 2) s = g_trS[L][tid];
            else {
                s = 0.f;
                #pragma unroll
                for (int p = 0; p < 16; p++) s += g_s2p[p][tid];
            }
            shS[tid] = s;
        }
        __syncthreads();
        for (int f = tid; f < n * n; f += 256) {
            int u = f / n, v = f - u * n;
            float su, cu, sv, cv;
            sincosf(-6.283185307179586f * (float)u / (float)n, &su, &cu);
            sincosf(-6.283185307179586f * (float)v / (float)n, &sv, &cv);
            float2 eu = make_float2(cu, su), ev = make_float2(cv, sv);
            float2 pU[3] = {make_float2(1.f, 0.f), eu, cmul(eu, eu)};
            float2 pV[3] = {make_float2(1.f, 0.f), ev, cmul(ev, ev)};
            float2 ph[9];
            #pragma unroll
            for (int dy = 0; dy < 3; dy++)
                #pragma unroll
                for (int dx = 0; dx < 3; dx++) ph[dy * 3 + dx] = cmul(pU[dy], pV[dx]);
            float2 T = make_float2(0.f, 0.f), T2 = make_float2(0.f, 0.f);
            #pragma unroll
            for (int a = 0; a < 9; a++) {
                T.x += shT[a] * ph[a].x;
                T.y += shT[a] * ph[a].y;
            }
            #pragma unroll
            for (int a = 0; a < 9; a++) {
                float2 inner = make_float2(0.f, 0.f);
                #pragma unroll
                for (int b = 0; b < 9; b++) {
                    float s = shS[a * 9 + b];
                    inner.x += s * ph[b].x;
                    inner.y += s * ph[b].y;
                }
                float2 pi = cmul(ph[a], inner);
                T2.x += pi.x;
                T2.y += pi.y;
            }
            float2 e1 = cmul(pU[1], pV[1]);
            e1.y = -e1.y;
            float2 e2 = cmul(e1, e1);
            float A = e1.x * T.x - e1.y * T.y;
            float B = e2.x * T2.x - e2.y * T2.y;
            part += 2.f * A - 1.5f * (float)c - 0.5f * B;
        }
        float as = 0.f;
        for (int k = tid; k < c; k += 256) as += als[k];
        part += (float)(n * n) * as;
    }
    float w = wred(part);
    if ((tid & 31) == 0) red[tid >> 5] = w;
    __syncthreads();
    if (tid == 0) {
        float s = 0.f;
        #pragma unroll
        for (int q = 0; q < 8; q++) s += red[q];
        stot = s;
    }
    __syncthreads();
    out[X_ELEMS + tid] = stot + g_tld[tid];
}

// ---------------- layer 0: fused FFMA conv (fast tanh epilogue) --------------
__global__ void __launch_bounds__(256, 2)
conv_layer0(const float* __restrict__ X, const float* __restrict__ Kw,
            const float* __restrict__ cb, const float* __restrict__ ab,
            const float* __restrict__ als, float* __restrict__ Y,
            __nv_bfloat16* __restrict__ YB) {
    constexpr int CPREV = 3, N = 64, CI_CHUNK = 12, OUT_BLK = 12;
    constexpr int CIN = 12, H = 128;
    constexpr int S_FLOATS = CI_CHUNK * 324 * 4;
    extern __shared__ float smem[];
    float* S = smem;
    float2* KS = (float2*)(smem + S_FLOATS);
    float* sE = (float*)(KS + CI_CHUNK * 9 * OUT_BLK);
    float* sAb = sE + OUT_BLK;

    const int tid = threadIdx.x;
    const int bq = blockIdx.x;
    const int b0 = bq * 4;
    constexpr int TILES_X = N / 16;
    const int ty = (blockIdx.y / TILES_X) * 16;
    const int tx = (blockIdx.y % TILES_X) * 16;
    const int py = tid >> 4, px = tid & 15;

    if (tid < OUT_BLK) {
        sE[tid] = expf(als[tid]);
        sAb[tid] = ab[tid];
    }

    unsigned long long accA[OUT_BLK], accB[OUT_BLK];
    #pragma unroll
    for (int o = 0; o < OUT_BLK; o++) { accA[o] = 0ull; accB[o] = 0ull; }

    {
        __syncthreads();
        for (int idx = tid; idx < CI_CHUNK * 324; idx += 256) {
            int ci = idx / 324;
            int rem = idx - ci * 324;
            int yy = rem / 18, xx = rem - yy * 18;
            int g = ci / CPREV;
            int cc = ci - g * CPREV;
            int gy = ty + yy - 1;
            if (gy < 0) gy += N;
            if (gy >= N) gy -= N;
            int gx = tx + xx - 1;
            if (gx < 0) gx += N;
            if (gx >= N) gx -= N;
            int sy = 2 * gy + (g & 1);
            int sx = 2 * gx + ((g ^ (g >> 1)) & 1);
            size_t base = ((size_t)cc * H + sy) * H + sx;
            size_t bstr = (size_t)CPREV * H * H;
            float4 val;
            val.x = X[base + (size_t)(b0 + 0) * bstr];
            val.y = X[base + (size_t)(b0 + 1) * bstr];
            val.z = X[base + (size_t)(b0 + 2) * bstr];
            val.w = X[base + (size_t)(b0 + 3) * bstr];
            *(float4*)(S + idx * 4) = val;
        }
        for (int idx = tid; idx < CI_CHUNK * 9 * OUT_BLK; idx += 256) {
            int ci = idx / (9 * OUT_BLK);
            int rem = idx - ci * 9 * OUT_BLK;
            int tap = rem / OUT_BLK;
            int o = rem - tap * OUT_BLK;
            float k = Kw[((size_t)o * CIN + ci) * 9 + tap];
            KS[idx] = make_float2(k, k);
        }
        __syncthreads();

        #pragma unroll 1
        for (int ci = 0; ci < CI_CHUNK; ci++) {
            const float* Sci = S + ci * 1296;
            const float2* Kci = KS + ci * 9 * OUT_BLK;
            #pragma unroll
            for (int tap = 0; tap < 9; tap++) {
                int dy = tap / 3, dx = tap - dy * 3;
                ulonglong2 v =
                    *(const ulonglong2*)(Sci + ((py + dy) * 18 + (px + dx)) * 4);
                #pragma unroll
                for (int o = 0; o < OUT_BLK; o += 2) {
                    ulonglong2 kk = *(const ulonglong2*)(Kci + tap * OUT_BLK + o);
                    ffma2(accA[o], kk.x, v.x);
                    ffma2(accB[o], kk.x, v.y);
                    ffma2(accA[o + 1], kk.y, v.x);
                    ffma2(accB[o + 1], kk.y, v.y);
                }
            }
        }
    }

    const int i = ty + py, j = tx + px;
    const int y = i >> 1, x = j >> 1;
    const int hs = i & 1, ws = j & 1;
    const int g = (hs == ws) ? hs : (2 + hs);
    const int p = y * 32 + x;
    float ld[4] = {0.f, 0.f, 0.f, 0.f};
    uint32_t pk[6][4];

    #pragma unroll
    for (int o = 0; o < OUT_BLK; o += 2) {
        float e0 = sE[o], a0v = sAb[o];
        float e1 = sE[o + 1], a1v = sAb[o + 1];
        float c0v = cb[((size_t)o * N + i) * N + j];
        float c1v = cb[((size_t)(o + 1) * N + i) * N + j];
        float2 pA0 = up2(accA[o]), pB0 = up2(accB[o]);
        float2 pA1 = up2(accA[o + 1]), pB1 = up2(accB[o + 1]);
        float z0[4] = {pA0.x, pA0.y, pB0.x, pB0.y};
        float z1[4] = {pA1.x, pA1.y, pB1.x, pB1.y};
        float t0[4], t1[4];
        #pragma unroll
        for (int nb = 0; nb < 4; nb++) {
            float l0, l1v;
            ftanh_ld((z0[nb] + c0v) * e0 + a0v, t0[nb], l0);
            ftanh_ld((z1[nb] + c1v) * e1 + a1v, t1[nb], l1v);
            ld[nb] += l0 + l1v;
            __nv_bfloat162 p2;
            p2.x = __float2bfloat16(t0[nb]);
            p2.y = __float2bfloat16(t1[nb]);
            pk[o >> 1][nb] = *(uint32_t*)&p2;
        }
        *(float4*)(Y + (((size_t)bq * 48 + g * 12 + o) * 1024 + p) * 4) =
            make_float4(t0[0], t0[1], t0[2], t0[3]);
        *(float4*)(Y + (((size_t)bq * 48 + g * 12 + o + 1) * 1024 + p) * 4) =
            make_float4(t1[0], t1[1], t1[2], t1[3]);
    }

    {
        #pragma unroll
        for (int nb = 0; nb < 4; nb++) {
            size_t base = ((size_t)(b0 + nb) * 1024 + p) * 64 + g * 12;
            *(uint2*)(YB + base) = make_uint2(pk[0][nb], pk[1][nb]);
            *(uint2*)(YB + base + 4) = make_uint2(pk[2][nb], pk[3][nb]);
            *(uint2*)(YB + base + 8) = make_uint2(pk[4][nb], pk[5][nb]);
        }
    }

    #pragma unroll
    for (int nb = 0; nb < 4; nb++) ld[nb] = wred(ld[nb]);
    __syncthreads();
    float* red = S;
    if ((tid & 31) == 0) {
        int w = tid >> 5;
        red[w * 4 + 0] = ld[0];
        red[w * 4 + 1] = ld[1];
        red[w * 4 + 2] = ld[2];
        red[w * 4 + 3] = ld[3];
    }
    __syncthreads();
    if (tid < 4) {
        float s = 0.f;
        #pragma unroll
        for (int w = 0; w < 8; w++) s += red[w * 4 + tid];
        atomicAdd(&g_tld[b0 + tid], s);
    }
}

// ---------------- layer 1: HMMA half-tile, 3 CTAs/SM ----------------
// Per CTA: 128 px (4 y-rows) x 48 co. Warp tile 32 px x 32 co (wm=wid&3, wn=wid>>2).
// smem: act halo 192 rows x 128B (24KB, staged once) + wt dbuf 2 x 8KB = 40960 B.
#define L1B_WT(s) (24576 + (s) * 8192)
#define L1_SMEM 40960

__device__ __forceinline__ void l1_stage_wt(uint32_t smem_base, int buf, int c, int tid) {
    const char* wbase = (const char*)(g_w1 + (size_t)c * 64 * 64);
    uint32_t ra = smem_base + L1B_WT(buf);
    #pragma unroll
    for (int s2 = tid; s2 < 512; s2 += 256) {
        uint32_t off = (uint32_t)s2 * 16;
        cpasync16(ra + swz(off), wbase + off);
    }
    cpasync_commit();
}

__global__ void __launch_bounds__(256, 3)
l1_mma(const __nv_bfloat16* __restrict__ ag, const float* __restrict__ x1p,
       const float* __restrict__ cb, const float* __restrict__ ab,
       const float* __restrict__ als,
       __nv_bfloat16* __restrict__ xg, float* __restrict__ xf) {
    extern __shared__ char smc[];
    __shared__ float sE[48], sAb[48], red[8];
    uint32_t smem_base = smem_u32(smc);
    const int tid = threadIdx.x;
    const int lane = tid & 31, wid = tid >> 5;
    const int b = blockIdx.x;
    const int pbase = blockIdx.y * 128;   // 128 px per CTA
    const int y0 = pbase >> 5;            // first y-row (0..28 step 4)
    const int wm = wid & 3;               // 4 m-tiles of 32 px
    const int wn = wid >> 2;              // 2 n-tiles of 32 co
    const int bq = b >> 2, nb = b & 3;

    if (tid < 48) {
        sE[tid] = expf(als[tid]);
        sAb[tid] = ab[tid];
    }

    // stage act halo: 6 y-rows x 32 x = 192 rows (staged ONCE)
    if (tid < 192) {
        int yrel = tid >> 5, x = tid & 31;
        int yg = (y0 - 1 + yrel) & 31;
        const char* src = (const char*)(ag + ((size_t)b * 1024 + yg * 32 + x) * 64);
        #pragma unroll
        for (int s = 0; s < 8; s++) {
            uint32_t off = (uint32_t)tid * 128 + s * 16;
            cpasync16(smem_base + swz(off), src + s * 16);
        }
    }
    l1_stage_wt(smem_base, 0, 0, tid);   // commits the group (act + wt0)

    float d[2][4][4];
    #pragma unroll
    for (int mt = 0; mt < 2; mt++)
        #pragma unroll
        for (int nt = 0; nt < 4; nt++)
            #pragma unroll
            for (int r = 0; r < 4; r++) d[mt][nt][r] = 0.f;

    int ply[2], plx[2];
    #pragma unroll
    for (int mt = 0; mt < 2; mt++) {
        int pl = wm * 32 + mt * 16 + (lane & 15);   // 0..127
        ply[mt] = pl >> 5;                           // 0..3
        plx[mt] = pl & 31;
    }

    #pragma unroll 1
    for (int c = 0; c < 9; c++) {
        int cur = c & 1;
        cpasync_wait<0>();
        __syncthreads();
        if (c + 1 < 9) l1_stage_wt(smem_base, 1 - cur, c + 1, tid);
        int dy = c / 3 - 1, dx = c % 3 - 1;
        uint32_t wtb = smem_base + L1B_WT(cur);
        #pragma unroll
        for (int ks = 0; ks < 4; ks++) {
            uint32_t a[2][4];
            #pragma unroll
            for (int mt = 0; mt < 2; mt++) {
                int row = (ply[mt] + 1 + dy) * 32 + ((plx[mt] + dx) & 31);
                uint32_t off = (uint32_t)row * 128 + ks * 32 + (lane >> 4) * 16;
                ldsm4(a[mt], smem_base + swz(off));
            }
            uint32_t bf[2][4];
            #pragma unroll
            for (int nh = 0; nh < 2; nh++) {
                uint32_t row = wn * 32 + nh * 16 + (lane & 7) + ((lane >> 4) << 3);
                uint32_t off = row * 128 + ks * 32 + ((lane >> 3) & 1) * 16;
                ldsm4(bf[nh], wtb + swz(off));
            }
            #pragma unroll
            for (int mt = 0; mt < 2; mt++)
                #pragma unroll
                for (int nt = 0; nt < 4; nt++)
                    mma16816(d[mt][nt], a[mt], &bf[nt >> 1][(nt & 1) * 2]);
        }
    }

    // epilogue: center add + cb + actnorm + fast tanh + logdet, write xg/xf
    float ldsum = 0.f;
    #pragma unroll
    for (int nt = 0; nt < 4; nt++) {
        int co = wn * 32 + nt * 8 + (lane & 3) * 2;
        if (co < 48) {
            float e0 = sE[co], e1 = sE[co + 1];
            float ab0 = sAb[co], ab1 = sAb[co + 1];
            const float* xc0p = x1p + ((size_t)bq * 48 + co) * 4096 + nb;
            const float* xc1p = x1p + ((size_t)bq * 48 + co + 1) * 4096 + nb;
            #pragma unroll
            for (int mt = 0; mt < 2; mt++) {
                #pragma unroll
                for (int half = 0; half < 2; half++) {
                    int p = pbase + wm * 32 + mt * 16 + (lane >> 2) + half * 8;
                    float xc0 = xc0p[p * 4];
                    float xc1 = xc1p[p * 4];
                    float z0 = d[mt][nt][half * 2] + xc0 + cb[(size_t)co * 1024 + p];
                    float z1 = d[mt][nt][half * 2 + 1] + xc1 + cb[(size_t)(co + 1) * 1024 + p];
                    float t0, t1, l0, l1v;
                    ftanh_ld(z0 * e0 + ab0, t0, l0);
                    ftanh_ld(z1 * e1 + ab1, t1, l1v);
                    ldsum += l0 + l1v;
                    int i = p >> 5, j = p & 31;
                    int y = i >> 1, x = j >> 1;
                    int hs = i & 1, ws = j & 1;
                    int g = (hs == ws) ? hs : (2 + hs);
                    size_t xi = ((size_t)b * 256 + y * 16 + x) * 192 + g * 48 + co;
                    __nv_bfloat162 pk2;
                    pk2.x = __float2bfloat16(t0);
                    pk2.y = __float2bfloat16(t1);
                    *(__nv_bfloat162*)(xg + xi) = pk2;
                    *(float2*)(xf + xi) = make_float2(t0, t1);
                }
            }
        }
    }
    ldsum = wred(ldsum);
    if (lane == 0) red[wid] = ldsum;
    __syncthreads();
    if (tid == 0) {
        float s = 0.f;
        #pragma unroll
        for (int w = 0; w < 8; w++) s += red[w];
        atomicAdd(&g_tld[b], s);
    }
}

// ---------------- layer 2: HMMA half-tile, 32px x 32co warp tiles (R16) ------
#define L2B_ACT(s) ((s) * 20480)
#define L2B_WT(s)  (40960 + (s) * 8192)
#define L2_SMEM 57344

__device__ __forceinline__ void l2_stage_act(uint32_t smem_base, int buf, int cc,
                                             const __nv_bfloat16* __restrict__ xg,
                                             int b, int y0, int tid) {
    for (int r = tid; r < 160; r += 256) {
        int yrel = r >> 4, xx = r & 15;
        int yg = (y0 - 1 + yrel) & 15;
        const char* src = (const char*)(xg + ((size_t)b * 256 + yg * 16 + xx) * 192 + cc * 64);
        uint32_t base = smem_base + L2B_ACT(buf);
        #pragma unroll
        for (int s = 0; s < 8; s++) {
            uint32_t off = (uint32_t)r * 128 + s * 16;
            cpasync16(base + swz(off), src + s * 16);
        }
    }
}

__device__ __forceinline__ void l2_stage_wt(uint32_t smem_base, int buf, int wc,
                                            int co0, int tid) {
    const char* wbase = (const char*)(g_w2 + ((size_t)wc * 192 + co0) * 64);
    uint32_t ra = smem_base + L2B_WT(buf);
    #pragma unroll
    for (int s2 = tid; s2 < 512; s2 += 256) {
        uint32_t off = (uint32_t)s2 * 16;
        cpasync16(ra + swz(off), wbase + off);
    }
}

__global__ void __launch_bounds__(256, 3)
l2_mma(const __nv_bfloat16* __restrict__ xg, const float* __restrict__ xf,
       const float* __restrict__ cb, const float* __restrict__ ab,
       const float* __restrict__ als, float* __restrict__ out) {
    extern __shared__ char smc[];
    __shared__ float sE[64], sAb[64];
    uint32_t smem_base = smem_u32(smc);
    const int tid = threadIdx.x;
    const int lane = tid & 31, wid = tid >> 5;
    const int b = blockIdx.x;
    const int mh = blockIdx.y;
    const int co0 = blockIdx.z * 64;
    const int y0 = mh * 8;
    const int wm = wid & 3;
    const int wn = wid >> 2;

    if (tid < 64) {
        sE[tid] = expf(als[co0 + tid]);
        sAb[tid] = ab[co0 + tid];
    }

    l2_stage_act(smem_base, 0, 0, xg, b, y0, tid);
    l2_stage_wt(smem_base, 0, 0, co0, tid);
    cpasync_commit();

    float d[2][4][4];
    #pragma unroll
    for (int mt = 0; mt < 2; mt++)
        #pragma unroll
        for (int nt = 0; nt < 4; nt++)
            #pragma unroll
            for (int r = 0; r < 4; r++) d[mt][nt][r] = 0.f;

    int ply[2], plx[2];
    #pragma unroll
    for (int mt = 0; mt < 2; mt++) {
        int pl = wm * 32 + mt * 16 + (lane & 15);
        ply[mt] = pl >> 4;
        plx[mt] = pl & 15;
    }

    #pragma unroll 1
    for (int k = 0; k < 27; k++) {
        int cur = k & 1;
        int cc = k / 9, tap = k - cc * 9;
        cpasync_wait<0>();
        __syncthreads();
        if (k + 1 < 27) {
            int k1 = k + 1;
            int cc1 = k1 / 9, tap1 = k1 - cc1 * 9;
            if (cc1 != cc) l2_stage_act(smem_base, cc1 & 1, cc1, xg, b, y0, tid);
            l2_stage_wt(smem_base, 1 - cur, tap1 * 3 + cc1, co0, tid);
            cpasync_commit();
        }
        int dy = tap / 3 - 1, dx = tap % 3 - 1;
        uint32_t actb = smem_base + L2B_ACT(cc & 1);
        uint32_t wtb = smem_base + L2B_WT(cur);
        #pragma unroll
        for (int ks = 0; ks < 4; ks++) {
            uint32_t a[2][4];
            #pragma unroll
            for (int mt = 0; mt < 2; mt++) {
                int row = (ply[mt] + 1 + dy) * 16 + ((plx[mt] + dx) & 15);
                uint32_t off = (uint32_t)row * 128 + ks * 32 + (lane >> 4) * 16;
                ldsm4(a[mt], actb + swz(off));
            }
            uint32_t bf[2][4];
            #pragma unroll
            for (int nh = 0; nh < 2; nh++) {
                uint32_t row = wn * 32 + nh * 16 + (lane & 7) + ((lane >> 4) << 3);
                uint32_t off = row * 128 + ks * 32 + ((lane >> 3) & 1) * 16;
                ldsm4(bf[nh], wtb + swz(off));
            }
            #pragma unroll
            for (int mt = 0; mt < 2; mt++)
                #pragma unroll
                for (int nt = 0; nt < 4; nt++)
                    mma16816(d[mt][nt], a[mt], &bf[nt >> 1][(nt & 1) * 2]);
        }
    }

    #pragma unroll
    for (int nt = 0; nt < 4; nt++) {
        int cr = wn * 32 + (nt >> 1) * 16 + (nt & 1) * 8 + (lane & 3) * 2;
        int co = co0 + cr;
        float e0 = sE[cr], e1 = sE[cr + 1];
        float ab0 = sAb[cr], ab1 = sAb[cr + 1];
        const float* cb0p = cb + (size_t)co * 256;
        const float* cb1p = cb + (size_t)(co + 1) * 256;
        float* o0p = out + ((size_t)b * 192 + co) * 256;
        float* o1p = out + ((size_t)b * 192 + co + 1) * 256;
        #pragma unroll
        for (int mt = 0; mt < 2; mt++) {
            int p = mh * 128 + wm * 32 + mt * 16 + (lane >> 2);
            const float* xf0 = xf + ((size_t)b * 256 + p) * 192;
            const float* xf8 = xf + ((size_t)b * 256 + p + 8) * 192;
            o0p[p] = (d[mt][nt][0] + xf0[co] + cb0p[p]) * e0 + ab0;
            o1p[p] = (d[mt][nt][1] + xf0[co + 1] + cb1p[p]) * e1 + ab1;
            o0p[p + 8] = (d[mt][nt][2] + xf8[co] + cb0p[p + 8]) * e0 + ab0;
            o1p[p + 8] = (d[mt][nt][3] + xf8[co + 1] + cb1p[p + 8]) * e1 + ab1;
        }
    }
}

// ---------------- launch ----------------
extern "C" void kernel_launch(void* const* d_in, const int* in_sizes, int n_in,
                              void* d_out, int out_size) {
    const float* x = (const float*)d_in[0];
    const float* k0 = (const float*)d_in[1];
    const float* cb0 = (const float*)d_in[2];
    const float* ab0 = (const float*)d_in[3];
    const float* als0 = (const float*)d_in[4];
    const float* k1 = (const float*)d_in[5];
    const float* cb1 = (const float*)d_in[6];
    const float* ab1 = (const float*)d_in[7];
    const float* als1 = (const float*)d_in[8];
    const float* k2 = (const float*)d_in[9];
    const float* cb2 = (const float*)d_in[10];
    const float* ab2 = (const float*)d_in[11];
    const float* als2 = (const float*)d_in[12];
    float* out = (float*)d_out;

    float *x1, *xf;
    __nv_bfloat16 *ag1, *xg;
    cudaGetSymbolAddress((void**)&x1, g_x1);
    cudaGetSymbolAddress((void**)&ag1, g_ag1);
    cudaGetSymbolAddress((void**)&xg, g_xg);
    cudaGetSymbolAddress((void**)&xf, g_xf32);

    const int SM0 = 12 * 324 * 4 * 4 + 12 * 9 * 12 * 8 + 12 * 2 * 4;
    cudaFuncSetAttribute((const void*)conv_layer0,
                         cudaFuncAttributeMaxDynamicSharedMemorySize, SM0);
    cudaFuncSetAttribute((const void*)l1_mma,
                         cudaFuncAttributeMaxDynamicSharedMemorySize, L1_SMEM);
    cudaFuncSetAttribute((const void*)l2_mma,
                         cudaFuncAttributeMaxDynamicSharedMemorySize, L2_SMEM);

    setup_kernel<<<2483, 256>>>(k0, k1, k2);
    conv_layer0<<<dim3(64, 16, 1), 256, SM0>>>(x, k0, cb0, ab0, als0, x1, ag1);
    l1_mma<<<dim3(256, 8), 256, L1_SMEM>>>(ag1, x1, cb1, ab1, als1, xg, xf);
    l2_mma<<<dim3(256, 2, 3), 256, L2_SMEM>>>(xg, xf, cb2, ab2, als2, out);
    fin_kernel<<<1, 256>>>(als0, als1, als2, out);
}